// round 10
// baseline (speedup 1.0000x reference)
#include <cuda_runtime.h>
#include <cstdint>

// Problem constants
#define BB 8
#define DD 256
#define NN 2048
#define HH 4
#define HD 64

// Scratch — __device__ globals per allocation rules
__device__ float g_q[BB * DD * NN];   // Q proj: tf32(0.125*val)
__device__ float g_k[BB * DD * NN];   // K proj: tf32
__device__ float g_v[BB * DD * NN];   // V proj: tf32, key-permuted in 8-groups
__device__ float g_x[BB * DD * NN];   // attention out (tf32-rounded)

__device__ __forceinline__ uint32_t f2tf32(float f) {
    uint32_t u;
    asm("cvt.rna.tf32.f32 %0, %1;" : "=r"(u) : "f"(f));
    return u;
}

__device__ __forceinline__ uint32_t smem_u32(const void* p) {
    uint32_t a;
    asm("{ .reg .u64 t; cvta.to.shared.u64 t, %1; cvt.u32.u64 %0, t; }"
        : "=r"(a) : "l"(p));
    return a;
}

__device__ __forceinline__ void cp16(uint32_t saddr, const float* g) {
    uint64_t ga;
    asm("cvta.to.global.u64 %0, %1;" : "=l"(ga) : "l"(g));
    asm volatile("cp.async.ca.shared.global [%0], [%1], 16;"
                 :: "r"(saddr), "l"(ga));
}
#define CP_COMMIT() asm volatile("cp.async.commit_group;" ::: "memory")
#define CP_WAIT0()  asm volatile("cp.async.wait_group 0;" ::: "memory")

// tf32 m16n8k8: D += A*B
__device__ __forceinline__ void mma_tf32(float d[4],
                                         uint32_t a0, uint32_t a1,
                                         uint32_t a2, uint32_t a3,
                                         uint32_t b0, uint32_t b1) {
    asm volatile(
        "mma.sync.aligned.m16n8k8.row.col.f32.tf32.tf32.f32 "
        "{%0,%1,%2,%3}, {%4,%5,%6,%7}, {%8,%9}, {%0,%1,%2,%3};"
        : "+f"(d[0]), "+f"(d[1]), "+f"(d[2]), "+f"(d[3])
        : "r"(a0), "r"(a1), "r"(a2), "r"(a3), "r"(b0), "r"(b1));
}

// ===========================================================================
// Projection GEMM body (R4-style staging: coalesced LDG + inline tf32 cvt +
// STS; 64-d chunks; paired (d,d+4) float2 smem layout).
// omode: 0 = plain fp32, 1 = tf32 bits, 2 = tf32(0.125*val),
//        4 = tf32 bits + key-permuted columns within 8-groups (for V)
// ===========================================================================
#define PJP 132
#define PJ_XPW (32 * PJP * 2)
#define PROJ_SMEM (2 * 32 * PJP * 8)  // 67,584 bytes

__device__ __forceinline__ void proj_body(
    const float* __restrict__ X, const float* __restrict__ W,
    const float* __restrict__ bias, float* __restrict__ out,
    int omode, int b, float* smf)
{
    uint32_t* smw = (uint32_t*)smf;

    const int tid  = threadIdx.x;
    const int warp = tid >> 5;
    const int lane = tid & 31;
    const int j    = lane & 3;
    const int r    = lane >> 2;

    const int o0 = blockIdx.y * 128;
    const int n0 = blockIdx.x * 128;
    const float* Xb = X + (size_t)b * DD * NN;
    const int qrow = warp * 16 + r;

    float acc[16][4];
#pragma unroll
    for (int nc = 0; nc < 16; nc++)
#pragma unroll
        for (int c = 0; c < 4; c++) acc[nc][c] = 0.f;

    for (int ch = 0; ch < 4; ch++) {
        const int d0c = ch * 64;
        if (ch) __syncthreads();
        for (int idx = tid; idx < 64 * 128; idx += 256) {
            const int d = idx >> 7;
            const int c = idx & 127;
            const int pr = (d >> 3) * 4 + (d & 3);
            const int e  = (d >> 2) & 1;
            smw[(pr * PJP + c) * 2 + e] =
                f2tf32(W[(size_t)(d0c + d) * DD + o0 + c]);
            smw[PJ_XPW + (pr * PJP + c) * 2 + e] =
                f2tf32(Xb[(size_t)(d0c + d) * NN + n0 + c]);
        }
        __syncthreads();

#pragma unroll
        for (int kc = 0; kc < 8; kc++) {
            const int pr = kc * 4 + j;
            const uint2 aA = *(const uint2*)&smw[(pr * PJP + qrow) * 2];
            const uint2 aB = *(const uint2*)&smw[(pr * PJP + qrow + 8) * 2];
#pragma unroll
            for (int nc = 0; nc < 16; nc++) {
                const uint2 bb =
                    *(const uint2*)&smw[PJ_XPW + (pr * PJP + nc * 8 + r) * 2];
                mma_tf32(acc[nc], aA.x, aB.x, aA.y, aB.y, bb.x, bb.y);
            }
        }
    }

    const float bi0 = bias[o0 + qrow];
    const float bi1 = bias[o0 + qrow + 8];
    float* row0 = out + (size_t)b * DD * NN + (size_t)(o0 + qrow) * NN + n0;
    float* row1 = row0 + 8 * NN;
#pragma unroll
    for (int nc = 0; nc < 16; nc++) {
        float v00 = acc[nc][0] + bi0, v01 = acc[nc][1] + bi0;
        float v10 = acc[nc][2] + bi1, v11 = acc[nc][3] + bi1;
        if (omode == 2) { v00 *= 0.125f; v01 *= 0.125f; v10 *= 0.125f; v11 *= 0.125f; }
        if (omode >= 1) {
            v00 = __uint_as_float(f2tf32(v00));
            v01 = __uint_as_float(f2tf32(v01));
            v10 = __uint_as_float(f2tf32(v10));
            v11 = __uint_as_float(f2tf32(v11));
        }
        if (omode == 4) {
            const int p0 = nc * 8 + j;
            const int p1 = nc * 8 + j + 4;
            row0[p0] = v00; row0[p1] = v01;
            row1[p0] = v10; row1[p1] = v11;
        } else {
            const int col = nc * 8 + 2 * j;
            *(float2*)&row0[col] = make_float2(v00, v01);
            *(float2*)&row1[col] = make_float2(v10, v11);
        }
    }
}

// Merged Q/K/V projection: z = which*8 + b
__global__ void __launch_bounds__(256, 2) proj_qkv_kernel(
    const float* __restrict__ Xq, const float* __restrict__ Wq,
    const float* __restrict__ bq,
    const float* __restrict__ Xk, const float* __restrict__ Wk,
    const float* __restrict__ bk,
    const float* __restrict__ Xv, const float* __restrict__ Wv,
    const float* __restrict__ bv)
{
    extern __shared__ float smf[];
    const int zz = blockIdx.z >> 3;
    const int b  = blockIdx.z & 7;
    if (zz == 0)      proj_body(Xq, Wq, bq, g_q, 2, b, smf);
    else if (zz == 1) proj_body(Xk, Wk, bk, g_k, 1, b, smf);
    else              proj_body(Xv, Wv, bv, g_v, 4, b, smf);
}

// Final projection (plain fp32 out)
__global__ void __launch_bounds__(256, 2) proj_out_kernel(
    const float* __restrict__ X, const float* __restrict__ W,
    const float* __restrict__ bias, float* __restrict__ out)
{
    extern __shared__ float smf[];
    proj_body(X, W, bias, out, 0, blockIdx.z, smf);
}

// ===========================================================================
// Fused attention (R7/R9 config: 256 threads, 8 warps x 16 query rows),
// all-tf32, P register-resident via key-permuted V, cp.async K/V double
// buffer, Q A-frags in registers. Output stored tf32-rounded.
// Softmax without max subtraction (scores bounded; exact math).
// ===========================================================================
#define QT 128
#define KTILE 64
#define NTILES (NN / KTILE)

#define AKS 72
#define AVS 68
#define KBW (64 * AKS)
#define VBW (64 * AVS)
#define OFF_K 0
#define OFF_V (2 * KBW)
#define ATTN_SMEM ((OFF_V + 2 * VBW) * 4)   // 71,680 bytes

__global__ void __launch_bounds__(256, 2) attn_mma_kernel(
    const float* __restrict__ Q, const float* __restrict__ K,
    const float* __restrict__ V, float* __restrict__ O)
{
    extern __shared__ float smf[];
    uint32_t* smw = (uint32_t*)smf;
    const uint32_t sb = smem_u32(smf);

    const int tid  = threadIdx.x;
    const int warp = tid >> 5;
    const int lane = tid & 31;
    const int j    = lane & 3;
    const int r    = lane >> 2;

    const int bid = blockIdx.x;
    const int q0  = (bid & 15) * QT;
    const int h   = (bid >> 4) & 3;
    const int b   = bid >> 6;
    const size_t base = (size_t)b * DD * NN + (size_t)h * NN;

    // copy mapping: thread covers one dh row, 16 consecutive key positions
    const int cr = tid >> 2;
    const int cs = (tid & 3) * 16;
    const float* Kgc = K + base + (size_t)cr * HH * NN + cs;
    const float* Vgc = V + base + (size_t)cr * HH * NN + cs;
    const uint32_t kaddr0 = sb + (OFF_K + cr * AKS + cs) * 4;
    const uint32_t vaddr0 = sb + (OFF_V + cr * AVS + cs) * 4;

#pragma unroll
    for (int i = 0; i < 4; i++) {
        cp16(kaddr0 + i * 16, Kgc + i * 4);
        cp16(vaddr0 + i * 16, Vgc + i * 4);
    }
    CP_COMMIT();

    // Q A-fragments in registers (once)
    const int qrow = warp * 16 + r;
    uint32_t qa[8][4];
    {
        const float* Qg = Q + base + q0 + qrow;
#pragma unroll
        for (int kc = 0; kc < 8; kc++) {
            const float* p0 = Qg + (size_t)(kc * 8 + j) * HH * NN;
            const float* p1 = Qg + (size_t)(kc * 8 + j + 4) * HH * NN;
            qa[kc][0] = __float_as_uint(p0[0]);
            qa[kc][1] = __float_as_uint(p0[8]);
            qa[kc][2] = __float_as_uint(p1[0]);
            qa[kc][3] = __float_as_uint(p1[8]);
        }
    }

    float oacc[8][4];
#pragma unroll
    for (int nc = 0; nc < 8; nc++)
#pragma unroll
        for (int c = 0; c < 4; c++) oacc[nc][c] = 0.f;
    float rs0 = 0.f, rs1 = 0.f;

    for (int t = 0; t < NTILES; t++) {
        const int cur = t & 1;

        CP_WAIT0();
        __syncthreads();

        if (t + 1 < NTILES) {
            const int nxt = (t + 1) & 1;
            const int kn = (t + 1) * KTILE;
#pragma unroll
            for (int i = 0; i < 4; i++) {
                cp16(kaddr0 + (nxt * KBW) * 4 + i * 16, Kgc + kn + i * 4);
                cp16(vaddr0 + (nxt * VBW) * 4 + i * 16, Vgc + kn + i * 4);
            }
            CP_COMMIT();
        }

        const uint32_t* Kb = smw + OFF_K + cur * KBW;
        const uint32_t* Vb = smw + OFF_V + cur * VBW;

        // ---- S = Q . K^T ----
        float s[8][4];
#pragma unroll
        for (int nc = 0; nc < 8; nc++)
#pragma unroll
            for (int c = 0; c < 4; c++) s[nc][c] = 0.f;

#pragma unroll
        for (int kc = 0; kc < 8; kc++) {
            const int d0 = kc * 8;
#pragma unroll
            for (int nc = 0; nc < 8; nc++) {
                const uint32_t b0 = Kb[(d0 + j) * AKS + nc * 8 + r];
                const uint32_t b1 = Kb[(d0 + j + 4) * AKS + nc * 8 + r];
                mma_tf32(s[nc], qa[kc][0], qa[kc][1], qa[kc][2], qa[kc][3],
                         b0, b1);
            }
        }

        // ---- exp (tf32-rounded), rowsums; P stays in registers ----
#pragma unroll
        for (int nc = 0; nc < 8; nc++) {
            const uint32_t u0 = f2tf32(__expf(s[nc][0]));
            const uint32_t u1 = f2tf32(__expf(s[nc][1]));
            const uint32_t u2 = f2tf32(__expf(s[nc][2]));
            const uint32_t u3 = f2tf32(__expf(s[nc][3]));
            rs0 += __uint_as_float(u0) + __uint_as_float(u1);
            rs1 += __uint_as_float(u2) + __uint_as_float(u3);
            s[nc][0] = __uint_as_float(u0);
            s[nc][1] = __uint_as_float(u1);
            s[nc][2] = __uint_as_float(u2);
            s[nc][3] = __uint_as_float(u3);
        }

        // ---- O += P . V  (C-frag (c0,c2,c1,c3) == A-frag; V key-permuted) ----
#pragma unroll
        for (int kc = 0; kc < 8; kc++) {
            const uint32_t a0 = __float_as_uint(s[kc][0]);
            const uint32_t a1 = __float_as_uint(s[kc][2]);
            const uint32_t a2 = __float_as_uint(s[kc][1]);
            const uint32_t a3 = __float_as_uint(s[kc][3]);
            const int kk = kc * 8;
#pragma unroll
            for (int nc = 0; nc < 8; nc++) {
                const uint32_t b0 = Vb[(nc * 8 + r) * AVS + kk + j];
                const uint32_t b1 = Vb[(nc * 8 + r) * AVS + kk + j + 4];
                mma_tf32(oacc[nc], a0, a1, a2, a3, b0, b1);
            }
        }
    }

    // rowsum across the quad
    rs0 += __shfl_xor_sync(0xffffffffu, rs0, 1);
    rs0 += __shfl_xor_sync(0xffffffffu, rs0, 2);
    rs1 += __shfl_xor_sync(0xffffffffu, rs1, 1);
    rs1 += __shfl_xor_sync(0xffffffffu, rs1, 2);
    const float inv0 = 1.0f / rs0;
    const float inv1 = 1.0f / rs1;

    // Stage normalized O as [q][dh] (stride 68), then store tf32-rounded
    __syncthreads();
#pragma unroll
    for (int nc = 0; nc < 8; nc++) {
        const int col = nc * 8 + 2 * j;
        smf[qrow * AVS + col]           = oacc[nc][0] * inv0;
        smf[qrow * AVS + col + 1]       = oacc[nc][1] * inv0;
        smf[(qrow + 8) * AVS + col]     = oacc[nc][2] * inv1;
        smf[(qrow + 8) * AVS + col + 1] = oacc[nc][3] * inv1;
    }
    __syncthreads();
    for (int idx = tid; idx < 64 * QT; idx += 256) {
        const int dh = idx >> 7;
        const int q  = idx & 127;
        O[base + (size_t)dh * HH * NN + q0 + q] =
            __uint_as_float(f2tf32(smf[q * AVS + dh]));
    }
}

// ===========================================================================
// Launch
// ===========================================================================
extern "C" void kernel_launch(void* const* d_in, const int* in_sizes, int n_in,
                              void* d_out, int out_size)
{
    const float* query = (const float*)d_in[0];
    const float* key   = (const float*)d_in[1];
    const float* value = (const float*)d_in[2];
    const float* Wq = (const float*)d_in[3];
    const float* bq = (const float*)d_in[4];
    const float* Wk = (const float*)d_in[5];
    const float* bk = (const float*)d_in[6];
    const float* Wv = (const float*)d_in[7];
    const float* bv = (const float*)d_in[8];
    const float* Wm = (const float*)d_in[9];
    const float* bm = (const float*)d_in[10];
    float* out = (float*)d_out;

    static float *pq = nullptr, *pk = nullptr, *pv = nullptr, *px = nullptr;
    static bool init_done = false;
    if (!init_done) {
        cudaGetSymbolAddress((void**)&pq, g_q);
        cudaGetSymbolAddress((void**)&pk, g_k);
        cudaGetSymbolAddress((void**)&pv, g_v);
        cudaGetSymbolAddress((void**)&px, g_x);
        cudaFuncSetAttribute(attn_mma_kernel,
                             cudaFuncAttributeMaxDynamicSharedMemorySize,
                             ATTN_SMEM);
        cudaFuncSetAttribute(proj_qkv_kernel,
                             cudaFuncAttributeMaxDynamicSharedMemorySize, PROJ_SMEM);
        cudaFuncSetAttribute(proj_out_kernel,
                             cudaFuncAttributeMaxDynamicSharedMemorySize, PROJ_SMEM);
        init_done = true;
    }

    dim3 qkvgrid(NN / 128, DD / 128, 3 * BB);   // (16, 2, 24) = 768 CTAs
    proj_qkv_kernel<<<qkvgrid, 256, PROJ_SMEM>>>(
        query, Wq, bq, key, Wk, bk, value, Wv, bv);

    attn_mma_kernel<<<BB * HH * (NN / 128), 256, ATTN_SMEM>>>(pq, pk, pv, px);

    dim3 ogrid(NN / 128, DD / 128, BB);         // (16, 2, 8)
    proj_out_kernel<<<ogrid, 256, PROJ_SMEM>>>(px, Wm, bm, out);
}

// round 11
// speedup vs baseline: 1.0533x; 1.0533x over previous
#include <cuda_runtime.h>
#include <cstdint>

// Problem constants
#define BB 8
#define DD 256
#define NN 2048
#define HH 4
#define HD 64

// Scratch — __device__ globals per allocation rules
__device__ float g_qi[BB * DD * NN];  // tf32-rounded raw inputs
__device__ float g_ki[BB * DD * NN];
__device__ float g_vi[BB * DD * NN];
__device__ float g_wq[DD * DD];       // tf32-rounded weights
__device__ float g_wk[DD * DD];
__device__ float g_wv[DD * DD];
__device__ float g_wm[DD * DD];
__device__ float g_q[BB * DD * NN];   // Q proj: tf32(0.125*val), natural layout
__device__ float g_k[BB * DD * NN];   // K proj: tf32, paired [b][h][pr][n][e]
__device__ float g_v[BB * DD * NN];   // V proj: tf32, natural layout
__device__ float g_x[BB * DD * NN];   // attention out (tf32-rounded)

__device__ __forceinline__ uint32_t f2tf32(float f) {
    uint32_t u;
    asm("cvt.rna.tf32.f32 %0, %1;" : "=r"(u) : "f"(f));
    return u;
}

__device__ __forceinline__ uint32_t smem_u32(const void* p) {
    uint32_t a;
    asm("{ .reg .u64 t; cvta.to.shared.u64 t, %1; cvt.u32.u64 %0, t; }"
        : "=r"(a) : "l"(p));
    return a;
}

__device__ __forceinline__ void cp16(uint32_t saddr, const float* g) {
    uint64_t ga;
    asm("cvta.to.global.u64 %0, %1;" : "=l"(ga) : "l"(g));
    asm volatile("cp.async.ca.shared.global [%0], [%1], 16;"
                 :: "r"(saddr), "l"(ga));
}
#define CP_COMMIT() asm volatile("cp.async.commit_group;" ::: "memory")
#define CP_WAIT0()  asm volatile("cp.async.wait_group 0;" ::: "memory")

// tf32 m16n8k8: D += A*B
__device__ __forceinline__ void mma_tf32(float d[4],
                                         uint32_t a0, uint32_t a1,
                                         uint32_t a2, uint32_t a3,
                                         uint32_t b0, uint32_t b1) {
    asm volatile(
        "mma.sync.aligned.m16n8k8.row.col.f32.tf32.tf32.f32 "
        "{%0,%1,%2,%3}, {%4,%5,%6,%7}, {%8,%9}, {%0,%1,%2,%3};"
        : "+f"(d[0]), "+f"(d[1]), "+f"(d[2]), "+f"(d[3])
        : "r"(a0), "r"(a1), "r"(a2), "r"(a3), "r"(b0), "r"(b1));
}

// ===========================================================================
// Prep: RNA-round inputs (q,k,v) and the four weight matrices to tf32 bits.
// ===========================================================================
__global__ void __launch_bounds__(256) prep_kernel(
    const float* __restrict__ q, const float* __restrict__ k,
    const float* __restrict__ v,
    const float* __restrict__ wq, const float* __restrict__ wk,
    const float* __restrict__ wv, const float* __restrict__ wm)
{
    const int i = blockIdx.x * 256 + threadIdx.x;   // float4 index
    if (i < (BB * DD * NN) / 4) {
        float4 a = ((const float4*)q)[i];
        float4 b = ((const float4*)k)[i];
        float4 c = ((const float4*)v)[i];
        a.x = __uint_as_float(f2tf32(a.x)); a.y = __uint_as_float(f2tf32(a.y));
        a.z = __uint_as_float(f2tf32(a.z)); a.w = __uint_as_float(f2tf32(a.w));
        b.x = __uint_as_float(f2tf32(b.x)); b.y = __uint_as_float(f2tf32(b.y));
        b.z = __uint_as_float(f2tf32(b.z)); b.w = __uint_as_float(f2tf32(b.w));
        c.x = __uint_as_float(f2tf32(c.x)); c.y = __uint_as_float(f2tf32(c.y));
        c.z = __uint_as_float(f2tf32(c.z)); c.w = __uint_as_float(f2tf32(c.w));
        ((float4*)g_qi)[i] = a;
        ((float4*)g_ki)[i] = b;
        ((float4*)g_vi)[i] = c;
    }
    if (i < (DD * DD) / 4) {
        float4 a = ((const float4*)wq)[i];
        float4 b = ((const float4*)wk)[i];
        float4 c = ((const float4*)wv)[i];
        float4 d = ((const float4*)wm)[i];
        a.x = __uint_as_float(f2tf32(a.x)); a.y = __uint_as_float(f2tf32(a.y));
        a.z = __uint_as_float(f2tf32(a.z)); a.w = __uint_as_float(f2tf32(a.w));
        b.x = __uint_as_float(f2tf32(b.x)); b.y = __uint_as_float(f2tf32(b.y));
        b.z = __uint_as_float(f2tf32(b.z)); b.w = __uint_as_float(f2tf32(b.w));
        c.x = __uint_as_float(f2tf32(c.x)); c.y = __uint_as_float(f2tf32(c.y));
        c.z = __uint_as_float(f2tf32(c.z)); c.w = __uint_as_float(f2tf32(c.w));
        d.x = __uint_as_float(f2tf32(d.x)); d.y = __uint_as_float(f2tf32(d.y));
        d.z = __uint_as_float(f2tf32(d.z)); d.w = __uint_as_float(f2tf32(d.w));
        ((float4*)g_wq)[i] = a;
        ((float4*)g_wk)[i] = b;
        ((float4*)g_wv)[i] = c;
        ((float4*)g_wm)[i] = d;
    }
}

// ===========================================================================
// Projection GEMM (R9 cp.async version): out = W^T X + b. Operands
// pre-rounded -> zero cvt in loop. 256 threads = 4 row-groups x 2 col-groups.
// OMODE: 0 = plain fp32, 1 = tf32 bits, 2 = tf32(0.125*val),
//        5 = tf32 bits + K-paired gmem layout [b][h][pr][n][e]
//            (pr = (dh>>3)*4 + (dh&3), e = (dh>>2)&1, dh = o>>2, h = o&3)
// ===========================================================================
#define PS 136
#define CHW (32 * PS)
#define PXO (2 * CHW)
#define PROJ_SMEM (4 * CHW * 4)          // 69,632 bytes

template <int OMODE>
__global__ void __launch_bounds__(256, 2) proj2_kernel(
    const float* __restrict__ X, const float* __restrict__ W,
    const float* __restrict__ bias, float* __restrict__ out)
{
    extern __shared__ float smf[];
    uint32_t* smw = (uint32_t*)smf;
    const uint32_t sb = smem_u32(smf);

    const int tid  = threadIdx.x;
    const int warp = tid >> 5;
    const int lane = tid & 31;
    const int j    = lane & 3;
    const int r    = lane >> 2;
    const int rg   = warp & 3;
    const int cg   = warp >> 2;

    const int b  = blockIdx.z;
    const int o0 = blockIdx.y * 128;
    const int n0 = blockIdx.x * 128;
    const float* Xb = X + (size_t)b * DD * NN;

    const int srow = tid >> 3;
    const int sseg = (tid & 7) * 16;
    const uint32_t wdst = sb + (srow * PS + sseg) * 4;
    const uint32_t xdst = sb + (PXO + srow * PS + sseg) * 4;

#pragma unroll
    for (int i = 0; i < 4; i++) {
        cp16(wdst + i * 16, W  + (size_t)srow * DD + o0 + sseg + i * 4);
        cp16(xdst + i * 16, Xb + (size_t)srow * NN + n0 + sseg + i * 4);
    }
    CP_COMMIT();

    float acc[2][8][4];
#pragma unroll
    for (int mt = 0; mt < 2; mt++)
#pragma unroll
        for (int nc = 0; nc < 8; nc++)
#pragma unroll
            for (int c = 0; c < 4; c++) acc[mt][nc][c] = 0.f;

    for (int ch = 0; ch < 8; ch++) {
        const int cur = ch & 1;
        CP_WAIT0();
        __syncthreads();

        if (ch + 1 < 8) {
            const int nxt = (ch + 1) & 1;
            const int d0c = (ch + 1) * 32;
#pragma unroll
            for (int i = 0; i < 4; i++) {
                cp16(wdst + nxt * CHW * 4 + i * 16,
                     W  + (size_t)(d0c + srow) * DD + o0 + sseg + i * 4);
                cp16(xdst + nxt * CHW * 4 + i * 16,
                     Xb + (size_t)(d0c + srow) * NN + n0 + sseg + i * 4);
            }
            CP_COMMIT();
        }

        const uint32_t* Wt = smw + cur * CHW;
        const uint32_t* Xt = smw + PXO + cur * CHW;

#pragma unroll
        for (int kc = 0; kc < 4; kc++) {
            const int d0 = kc * 8;
            uint32_t a[2][4];
#pragma unroll
            for (int mt = 0; mt < 2; mt++) {
                const int ob = rg * 32 + mt * 16 + r;
                a[mt][0] = Wt[(d0 + j) * PS + ob];
                a[mt][1] = Wt[(d0 + j) * PS + ob + 8];
                a[mt][2] = Wt[(d0 + j + 4) * PS + ob];
                a[mt][3] = Wt[(d0 + j + 4) * PS + ob + 8];
            }
#pragma unroll
            for (int nc = 0; nc < 8; nc++) {
                const int nb = cg * 64 + nc * 8 + r;
                const uint32_t b0 = Xt[(d0 + j) * PS + nb];
                const uint32_t b1 = Xt[(d0 + j + 4) * PS + nb];
                mma_tf32(acc[0][nc], a[0][0], a[0][1], a[0][2], a[0][3], b0, b1);
                mma_tf32(acc[1][nc], a[1][0], a[1][1], a[1][2], a[1][3], b0, b1);
            }
        }
        __syncthreads();
    }

#pragma unroll
    for (int mt = 0; mt < 2; mt++) {
        const int orow = o0 + rg * 32 + mt * 16 + r;
        const float bi0 = bias[orow];
        const float bi1 = bias[orow + 8];
#pragma unroll
        for (int nc = 0; nc < 8; nc++) {
            float v00 = acc[mt][nc][0] + bi0, v01 = acc[mt][nc][1] + bi0;
            float v10 = acc[mt][nc][2] + bi1, v11 = acc[mt][nc][3] + bi1;
            if (OMODE == 2) { v00 *= 0.125f; v01 *= 0.125f; v10 *= 0.125f; v11 *= 0.125f; }
            if (OMODE >= 1) {
                v00 = __uint_as_float(f2tf32(v00));
                v01 = __uint_as_float(f2tf32(v01));
                v10 = __uint_as_float(f2tf32(v10));
                v11 = __uint_as_float(f2tf32(v11));
            }
            const int ncol = n0 + cg * 64 + nc * 8 + 2 * j;
            if (OMODE == 5) {
                // K-paired layout: idx = b*DD*NN + h*64*NN + pr*2*NN + n*2 + e
#pragma unroll
                for (int rr = 0; rr < 2; rr++) {
                    const int o = orow + rr * 8;
                    const int h  = o & 3;
                    const int dh = o >> 2;
                    const int pr = ((dh >> 3) << 2) | (dh & 3);
                    const int e  = (dh >> 2) & 1;
                    float* dst = out + (size_t)b * DD * NN
                               + (size_t)h * 64 * NN + (size_t)pr * 2 * NN + e;
                    const float a0 = rr ? v10 : v00;
                    const float a1 = rr ? v11 : v01;
                    dst[(size_t)ncol * 2]       = a0;
                    dst[(size_t)(ncol + 1) * 2] = a1;
                }
            } else {
                float* row0 = out + (size_t)b * DD * NN + (size_t)orow * NN + ncol;
                float* row1 = row0 + 8 * NN;
                *(float2*)row0 = make_float2(v00, v01);
                *(float2*)row1 = make_float2(v10, v11);
            }
        }
    }
}

// ===========================================================================
// Fused attention: 256 threads, 8 warps x 16 query rows, all-tf32,
// P register-resident. NEW: all B-fragments via LDS.64 —
//  - K staged from paired gmem layout [pr][n][e]; stride 136 words/pr-row.
//  - V natural layout; PV pair (pos j, j+4) == consecutive keys (2j, 2j+1)
//    through the key permutation, adjacent in [dh][token]; stride 72.
// cp.async K/V double buffer; Q A-frags in registers. Softmax without max
// subtraction (scores bounded; exact math). Output stored tf32-rounded.
// ===========================================================================
#define QT 128
#define KTILE 64
#define NTILES (NN / KTILE)

#define AK2 136                       // K words per pr-row (128 + 8 pad)
#define AVS 72                        // V words per dh-row (64 + 8 pad)
#define KBW (32 * AK2)                // 4352 words / K buffer
#define VBW (64 * AVS)                // 4608 words / V buffer
#define OFF_K 0
#define OFF_V (2 * KBW)               // 8704
#define ATTN_SMEM ((OFF_V + 2 * VBW) * 4)   // 71,680 bytes

__global__ void __launch_bounds__(256, 2) attn_mma_kernel(
    const float* __restrict__ Q, const float* __restrict__ K,
    const float* __restrict__ V, float* __restrict__ O)
{
    extern __shared__ float smf[];
    uint32_t* smw = (uint32_t*)smf;
    const uint32_t sb = smem_u32(smf);

    const int tid  = threadIdx.x;
    const int warp = tid >> 5;
    const int lane = tid & 31;
    const int j    = lane & 3;
    const int r    = lane >> 2;

    const int bid = blockIdx.x;
    const int q0  = (bid & 15) * QT;
    const int h   = (bid >> 4) & 3;
    const int b   = bid >> 6;
    const size_t base = (size_t)b * DD * NN + (size_t)h * NN;

    // K staging: thread covers one pr-row, 16 consecutive words of [n][e]
    const int kr   = tid >> 3;
    const int kseg = (tid & 7) * 16;
    const float* Kgc = K + (size_t)b * DD * NN + (size_t)h * 64 * NN
                     + (size_t)kr * 2 * NN + kseg;
    const uint32_t kaddr0 = sb + (OFF_K + kr * AK2 + kseg) * 4;
    // V staging: thread covers one dh-row, 16 consecutive keys
    const int vr   = tid >> 2;
    const int vseg = (tid & 3) * 16;
    const float* Vgc = V + base + (size_t)vr * HH * NN + vseg;
    const uint32_t vaddr0 = sb + (OFF_V + vr * AVS + vseg) * 4;

#pragma unroll
    for (int i = 0; i < 4; i++) {
        cp16(kaddr0 + i * 16, Kgc + i * 4);
        cp16(vaddr0 + i * 16, Vgc + i * 4);
    }
    CP_COMMIT();

    // Q A-fragments in registers (once)
    const int qrow = warp * 16 + r;
    uint32_t qa[8][4];
    {
        const float* Qg = Q + base + q0 + qrow;
#pragma unroll
        for (int kc = 0; kc < 8; kc++) {
            const float* p0 = Qg + (size_t)(kc * 8 + j) * HH * NN;
            const float* p1 = Qg + (size_t)(kc * 8 + j + 4) * HH * NN;
            qa[kc][0] = __float_as_uint(p0[0]);
            qa[kc][1] = __float_as_uint(p0[8]);
            qa[kc][2] = __float_as_uint(p1[0]);
            qa[kc][3] = __float_as_uint(p1[8]);
        }
    }

    float oacc[8][4];
#pragma unroll
    for (int nc = 0; nc < 8; nc++)
#pragma unroll
        for (int c = 0; c < 4; c++) oacc[nc][c] = 0.f;
    float rs0 = 0.f, rs1 = 0.f;

    for (int t = 0; t < NTILES; t++) {
        const int cur = t & 1;

        CP_WAIT0();
        __syncthreads();

        if (t + 1 < NTILES) {
            const int nxt = (t + 1) & 1;
            const int kn = (t + 1) * KTILE;
#pragma unroll
            for (int i = 0; i < 4; i++) {
                cp16(kaddr0 + (nxt * KBW) * 4 + i * 16, Kgc + kn * 2 + i * 4);
                cp16(vaddr0 + (nxt * VBW) * 4 + i * 16, Vgc + kn + i * 4);
            }
            CP_COMMIT();
        }

        const uint32_t* Kb = smw + OFF_K + cur * KBW;
        const uint32_t* Vb = smw + OFF_V + cur * VBW;

        // ---- S = Q . K^T  (B-pairs via LDS.64 from paired K) ----
        float s[8][4];
#pragma unroll
        for (int nc = 0; nc < 8; nc++)
#pragma unroll
            for (int c = 0; c < 4; c++) s[nc][c] = 0.f;

#pragma unroll
        for (int kc = 0; kc < 8; kc++) {
            const int pr = kc * 4 + j;
#pragma unroll
            for (int nc = 0; nc < 8; nc++) {
                const uint2 bb =
                    *(const uint2*)&Kb[pr * AK2 + (nc * 8 + r) * 2];
                mma_tf32(s[nc], qa[kc][0], qa[kc][1], qa[kc][2], qa[kc][3],
                         bb.x, bb.y);
            }
        }

        // ---- exp (tf32-rounded), rowsums; P stays in registers ----
#pragma unroll
        for (int nc = 0; nc < 8; nc++) {
            const uint32_t u0 = f2tf32(__expf(s[nc][0]));
            const uint32_t u1 = f2tf32(__expf(s[nc][1]));
            const uint32_t u2 = f2tf32(__expf(s[nc][2]));
            const uint32_t u3 = f2tf32(__expf(s[nc][3]));
            rs0 += __uint_as_float(u0) + __uint_as_float(u1);
            rs1 += __uint_as_float(u2) + __uint_as_float(u3);
            s[nc][0] = __uint_as_float(u0);
            s[nc][1] = __uint_as_float(u1);
            s[nc][2] = __uint_as_float(u2);
            s[nc][3] = __uint_as_float(u3);
        }

        // ---- O += P . V : A-frag = (c0,c2,c1,c3); B-pair = consecutive
        //      keys (2j, 2j+1) via LDS.64 from natural V ----
#pragma unroll
        for (int kc = 0; kc < 8; kc++) {
            const uint32_t a0 = __float_as_uint(s[kc][0]);
            const uint32_t a1 = __float_as_uint(s[kc][2]);
            const uint32_t a2 = __float_as_uint(s[kc][1]);
            const uint32_t a3 = __float_as_uint(s[kc][3]);
            const int kk = kc * 8 + 2 * j;
#pragma unroll
            for (int nc = 0; nc < 8; nc++) {
                const uint2 vb =
                    *(const uint2*)&Vb[(nc * 8 + r) * AVS + kk];
                mma_tf32(oacc[nc], a0, a1, a2, a3, vb.x, vb.y);
            }
        }
    }

    // rowsum across the quad
    rs0 += __shfl_xor_sync(0xffffffffu, rs0, 1);
    rs0 += __shfl_xor_sync(0xffffffffu, rs0, 2);
    rs1 += __shfl_xor_sync(0xffffffffu, rs1, 1);
    rs1 += __shfl_xor_sync(0xffffffffu, rs1, 2);
    const float inv0 = 1.0f / rs0;
    const float inv1 = 1.0f / rs1;

    // Stage normalized O as [q][dh] (stride 68), then store tf32-rounded
    __syncthreads();
#pragma unroll
    for (int nc = 0; nc < 8; nc++) {
        const int col = nc * 8 + 2 * j;
        smf[qrow * 68 + col]           = oacc[nc][0] * inv0;
        smf[qrow * 68 + col + 1]       = oacc[nc][1] * inv0;
        smf[(qrow + 8) * 68 + col]     = oacc[nc][2] * inv1;
        smf[(qrow + 8) * 68 + col + 1] = oacc[nc][3] * inv1;
    }
    __syncthreads();
    for (int idx = tid; idx < 64 * QT; idx += 256) {
        const int dh = idx >> 7;
        const int q  = idx & 127;
        O[base + (size_t)dh * HH * NN + q0 + q] =
            __uint_as_float(f2tf32(smf[q * 68 + dh]));
    }
}

// ===========================================================================
// Launch
// ===========================================================================
extern "C" void kernel_launch(void* const* d_in, const int* in_sizes, int n_in,
                              void* d_out, int out_size)
{
    const float* query = (const float*)d_in[0];
    const float* key   = (const float*)d_in[1];
    const float* value = (const float*)d_in[2];
    const float* Wq = (const float*)d_in[3];
    const float* bq = (const float*)d_in[4];
    const float* Wk = (const float*)d_in[5];
    const float* bk = (const float*)d_in[6];
    const float* Wv = (const float*)d_in[7];
    const float* bv = (const float*)d_in[8];
    const float* Wm = (const float*)d_in[9];
    const float* bm = (const float*)d_in[10];
    float* out = (float*)d_out;

    static float *pqi = nullptr, *pki = nullptr, *pvi = nullptr;
    static float *pwq = nullptr, *pwk = nullptr, *pwv = nullptr, *pwm = nullptr;
    static float *pq = nullptr, *pk = nullptr, *pv = nullptr, *px = nullptr;
    static bool init_done = false;
    if (!init_done) {
        cudaGetSymbolAddress((void**)&pqi, g_qi);
        cudaGetSymbolAddress((void**)&pki, g_ki);
        cudaGetSymbolAddress((void**)&pvi, g_vi);
        cudaGetSymbolAddress((void**)&pwq, g_wq);
        cudaGetSymbolAddress((void**)&pwk, g_wk);
        cudaGetSymbolAddress((void**)&pwv, g_wv);
        cudaGetSymbolAddress((void**)&pwm, g_wm);
        cudaGetSymbolAddress((void**)&pq,  g_q);
        cudaGetSymbolAddress((void**)&pk,  g_k);
        cudaGetSymbolAddress((void**)&pv,  g_v);
        cudaGetSymbolAddress((void**)&px,  g_x);
        cudaFuncSetAttribute(attn_mma_kernel,
                             cudaFuncAttributeMaxDynamicSharedMemorySize,
                             ATTN_SMEM);
        cudaFuncSetAttribute(proj2_kernel<0>,
                             cudaFuncAttributeMaxDynamicSharedMemorySize, PROJ_SMEM);
        cudaFuncSetAttribute(proj2_kernel<1>,
                             cudaFuncAttributeMaxDynamicSharedMemorySize, PROJ_SMEM);
        cudaFuncSetAttribute(proj2_kernel<2>,
                             cudaFuncAttributeMaxDynamicSharedMemorySize, PROJ_SMEM);
        cudaFuncSetAttribute(proj2_kernel<5>,
                             cudaFuncAttributeMaxDynamicSharedMemorySize, PROJ_SMEM);
        init_done = true;
    }

    prep_kernel<<<(BB * DD * NN / 4 + 255) / 256, 256>>>(
        query, key, value, Wq, Wk, Wv, Wm);

    dim3 pgrid(NN / 128, DD / 128, BB);   // (16, 2, 8)
    proj2_kernel<2><<<pgrid, 256, PROJ_SMEM>>>(pqi, pwq, bq, pq);
    proj2_kernel<5><<<pgrid, 256, PROJ_SMEM>>>(pki, pwk, bk, pk);
    proj2_kernel<1><<<pgrid, 256, PROJ_SMEM>>>(pvi, pwv, bv, pv);

    attn_mma_kernel<<<BB * HH * (NN / 128), 256, ATTN_SMEM>>>(pq, pk, pv, px);

    proj2_kernel<0><<<pgrid, 256, PROJ_SMEM>>>(px, pwm, bm, out);
}

// round 12
// speedup vs baseline: 1.0624x; 1.0086x over previous
#include <cuda_runtime.h>
#include <cstdint>

// Problem constants
#define BB 8
#define DD 256
#define NN 2048
#define HH 4
#define HD 64

// Scratch — __device__ globals per allocation rules
__device__ float g_qi[BB * DD * NN];  // tf32-rounded raw inputs
__device__ float g_ki[BB * DD * NN];
__device__ float g_vi[BB * DD * NN];
__device__ float g_wq[DD * DD];       // tf32-rounded weights
__device__ float g_wk[DD * DD];
__device__ float g_wv[DD * DD];
__device__ float g_wm[DD * DD];
__device__ float g_q[BB * DD * NN];   // Q proj: tf32(0.125*val), natural layout
__device__ float g_k[BB * DD * NN];   // K proj: tf32, paired [b][h][pr][n][e]
__device__ float g_v[BB * DD * NN];   // V proj: tf32, natural layout
__device__ float g_x[BB * DD * NN];   // attention out (tf32-rounded)

__device__ __forceinline__ uint32_t f2tf32(float f) {
    uint32_t u;
    asm("cvt.rna.tf32.f32 %0, %1;" : "=r"(u) : "f"(f));
    return u;
}

__device__ __forceinline__ uint32_t smem_u32(const void* p) {
    uint32_t a;
    asm("{ .reg .u64 t; cvta.to.shared.u64 t, %1; cvt.u32.u64 %0, t; }"
        : "=r"(a) : "l"(p));
    return a;
}

__device__ __forceinline__ void cp16(uint32_t saddr, const float* g) {
    uint64_t ga;
    asm("cvta.to.global.u64 %0, %1;" : "=l"(ga) : "l"(g));
    asm volatile("cp.async.ca.shared.global [%0], [%1], 16;"
                 :: "r"(saddr), "l"(ga));
}
#define CP_COMMIT() asm volatile("cp.async.commit_group;" ::: "memory")
#define CP_WAIT0()  asm volatile("cp.async.wait_group 0;" ::: "memory")

// tf32 m16n8k8: D += A*B
__device__ __forceinline__ void mma_tf32(float d[4],
                                         uint32_t a0, uint32_t a1,
                                         uint32_t a2, uint32_t a3,
                                         uint32_t b0, uint32_t b1) {
    asm volatile(
        "mma.sync.aligned.m16n8k8.row.col.f32.tf32.tf32.f32 "
        "{%0,%1,%2,%3}, {%4,%5,%6,%7}, {%8,%9}, {%0,%1,%2,%3};"
        : "+f"(d[0]), "+f"(d[1]), "+f"(d[2]), "+f"(d[3])
        : "r"(a0), "r"(a1), "r"(a2), "r"(a3), "r"(b0), "r"(b1));
}

// ===========================================================================
// Prep: RNA-round inputs (q,k,v) and the four weight matrices to tf32 bits.
// ===========================================================================
__global__ void __launch_bounds__(256) prep_kernel(
    const float* __restrict__ q, const float* __restrict__ k,
    const float* __restrict__ v,
    const float* __restrict__ wq, const float* __restrict__ wk,
    const float* __restrict__ wv, const float* __restrict__ wm)
{
    const int i = blockIdx.x * 256 + threadIdx.x;   // float4 index
    if (i < (BB * DD * NN) / 4) {
        float4 a = ((const float4*)q)[i];
        float4 b = ((const float4*)k)[i];
        float4 c = ((const float4*)v)[i];
        a.x = __uint_as_float(f2tf32(a.x)); a.y = __uint_as_float(f2tf32(a.y));
        a.z = __uint_as_float(f2tf32(a.z)); a.w = __uint_as_float(f2tf32(a.w));
        b.x = __uint_as_float(f2tf32(b.x)); b.y = __uint_as_float(f2tf32(b.y));
        b.z = __uint_as_float(f2tf32(b.z)); b.w = __uint_as_float(f2tf32(b.w));
        c.x = __uint_as_float(f2tf32(c.x)); c.y = __uint_as_float(f2tf32(c.y));
        c.z = __uint_as_float(f2tf32(c.z)); c.w = __uint_as_float(f2tf32(c.w));
        ((float4*)g_qi)[i] = a;
        ((float4*)g_ki)[i] = b;
        ((float4*)g_vi)[i] = c;
    }
    if (i < (DD * DD) / 4) {
        float4 a = ((const float4*)wq)[i];
        float4 b = ((const float4*)wk)[i];
        float4 c = ((const float4*)wv)[i];
        float4 d = ((const float4*)wm)[i];
        a.x = __uint_as_float(f2tf32(a.x)); a.y = __uint_as_float(f2tf32(a.y));
        a.z = __uint_as_float(f2tf32(a.z)); a.w = __uint_as_float(f2tf32(a.w));
        b.x = __uint_as_float(f2tf32(b.x)); b.y = __uint_as_float(f2tf32(b.y));
        b.z = __uint_as_float(f2tf32(b.z)); b.w = __uint_as_float(f2tf32(b.w));
        c.x = __uint_as_float(f2tf32(c.x)); c.y = __uint_as_float(f2tf32(c.y));
        c.z = __uint_as_float(f2tf32(c.z)); c.w = __uint_as_float(f2tf32(c.w));
        d.x = __uint_as_float(f2tf32(d.x)); d.y = __uint_as_float(f2tf32(d.y));
        d.z = __uint_as_float(f2tf32(d.z)); d.w = __uint_as_float(f2tf32(d.w));
        ((float4*)g_wq)[i] = a;
        ((float4*)g_wk)[i] = b;
        ((float4*)g_wv)[i] = c;
        ((float4*)g_wm)[i] = d;
    }
}

// ===========================================================================
// Projection GEMM body (cp.async, zero cvt in loop). Operands pre-rounded.
// OTILE = o-rows per CTA (128 or 64). 256 threads = 4 rg x 2 cg.
// omode: 0 = plain fp32, 1 = tf32 bits, 2 = tf32(0.125*val),
//        5 = tf32 bits + K-paired gmem layout [b][h][pr][n][e]
// ===========================================================================
#define PS 136
#define CHW (32 * PS)
#define PXO (2 * CHW)
#define PROJ_SMEM (4 * CHW * 4)          // 69,632 bytes

template <int OTILE>
__device__ __forceinline__ void proj_body(
    const float* __restrict__ X, const float* __restrict__ W,
    const float* __restrict__ bias, float* __restrict__ out,
    int omode, int b, float* smf)
{
    constexpr int MT = OTILE / 64;       // 2 for OTILE=128, 1 for OTILE=64
    uint32_t* smw = (uint32_t*)smf;
    const uint32_t sb = smem_u32(smf);

    const int tid  = threadIdx.x;
    const int warp = tid >> 5;
    const int lane = tid & 31;
    const int j    = lane & 3;
    const int r    = lane >> 2;
    const int rg   = warp & 3;
    const int cg   = warp >> 2;

    const int o0 = blockIdx.y * OTILE;
    const int n0 = blockIdx.x * 128;
    const float* Xb = X + (size_t)b * DD * NN;

    const int srow = tid >> 3;
    const int ssegx = (tid & 7) * 16;                 // X: 16 cols/thread
    const int ssegw = (tid & 7) * (OTILE / 8);        // W: OTILE/8 cols/thread
    const uint32_t wdst = sb + (srow * PS + ssegw) * 4;
    const uint32_t xdst = sb + (PXO + srow * PS + ssegx) * 4;

#pragma unroll
    for (int i = 0; i < OTILE / 32; i++)
        cp16(wdst + i * 16, W + (size_t)srow * DD + o0 + ssegw + i * 4);
#pragma unroll
    for (int i = 0; i < 4; i++)
        cp16(xdst + i * 16, Xb + (size_t)srow * NN + n0 + ssegx + i * 4);
    CP_COMMIT();

    float acc[MT][8][4];
#pragma unroll
    for (int mt = 0; mt < MT; mt++)
#pragma unroll
        for (int nc = 0; nc < 8; nc++)
#pragma unroll
            for (int c = 0; c < 4; c++) acc[mt][nc][c] = 0.f;

    for (int ch = 0; ch < 8; ch++) {
        const int cur = ch & 1;
        CP_WAIT0();
        __syncthreads();

        if (ch + 1 < 8) {
            const int nxt = (ch + 1) & 1;
            const int d0c = (ch + 1) * 32;
#pragma unroll
            for (int i = 0; i < OTILE / 32; i++)
                cp16(wdst + nxt * CHW * 4 + i * 16,
                     W + (size_t)(d0c + srow) * DD + o0 + ssegw + i * 4);
#pragma unroll
            for (int i = 0; i < 4; i++)
                cp16(xdst + nxt * CHW * 4 + i * 16,
                     Xb + (size_t)(d0c + srow) * NN + n0 + ssegx + i * 4);
            CP_COMMIT();
        }

        const uint32_t* Wt = smw + cur * CHW;
        const uint32_t* Xt = smw + PXO + cur * CHW;

#pragma unroll
        for (int kc = 0; kc < 4; kc++) {
            const int d0 = kc * 8;
            uint32_t a[MT][4];
#pragma unroll
            for (int mt = 0; mt < MT; mt++) {
                const int ob = rg * (OTILE / 4) + mt * 16 + r;
                a[mt][0] = Wt[(d0 + j) * PS + ob];
                a[mt][1] = Wt[(d0 + j) * PS + ob + 8];
                a[mt][2] = Wt[(d0 + j + 4) * PS + ob];
                a[mt][3] = Wt[(d0 + j + 4) * PS + ob + 8];
            }
#pragma unroll
            for (int nc = 0; nc < 8; nc++) {
                const int nb = cg * 64 + nc * 8 + r;
                const uint32_t b0 = Xt[(d0 + j) * PS + nb];
                const uint32_t b1 = Xt[(d0 + j + 4) * PS + nb];
#pragma unroll
                for (int mt = 0; mt < MT; mt++)
                    mma_tf32(acc[mt][nc], a[mt][0], a[mt][1], a[mt][2],
                             a[mt][3], b0, b1);
            }
        }
        __syncthreads();
    }

#pragma unroll
    for (int mt = 0; mt < MT; mt++) {
        const int orow = o0 + rg * (OTILE / 4) + mt * 16 + r;
        const float bi0 = bias[orow];
        const float bi1 = bias[orow + 8];
#pragma unroll
        for (int nc = 0; nc < 8; nc++) {
            float v00 = acc[mt][nc][0] + bi0, v01 = acc[mt][nc][1] + bi0;
            float v10 = acc[mt][nc][2] + bi1, v11 = acc[mt][nc][3] + bi1;
            if (omode == 2) { v00 *= 0.125f; v01 *= 0.125f; v10 *= 0.125f; v11 *= 0.125f; }
            if (omode >= 1) {
                v00 = __uint_as_float(f2tf32(v00));
                v01 = __uint_as_float(f2tf32(v01));
                v10 = __uint_as_float(f2tf32(v10));
                v11 = __uint_as_float(f2tf32(v11));
            }
            const int ncol = n0 + cg * 64 + nc * 8 + 2 * j;
            if (omode == 5) {
                // K-paired layout: idx = b*DD*NN + h*64*NN + pr*2*NN + n*2 + e
#pragma unroll
                for (int rr = 0; rr < 2; rr++) {
                    const int o = orow + rr * 8;
                    const int h  = o & 3;
                    const int dh = o >> 2;
                    const int pr = ((dh >> 3) << 2) | (dh & 3);
                    const int e  = (dh >> 2) & 1;
                    float* dst = out + (size_t)b * DD * NN
                               + (size_t)h * 64 * NN + (size_t)pr * 2 * NN + e;
                    const float a0 = rr ? v10 : v00;
                    const float a1 = rr ? v11 : v01;
                    dst[(size_t)ncol * 2]       = a0;
                    dst[(size_t)(ncol + 1) * 2] = a1;
                }
            } else {
                float* row0 = out + (size_t)b * DD * NN + (size_t)orow * NN + ncol;
                float* row1 = row0 + 8 * NN;
                *(float2*)row0 = make_float2(v00, v01);
                *(float2*)row1 = make_float2(v10, v11);
            }
        }
    }
}

// Merged Q/K/V projection: z = which*8 + b. 768 CTAs -> 2.6 waves.
__global__ void __launch_bounds__(256, 2) proj_qkv_kernel(
    const float* __restrict__ bq, const float* __restrict__ bk,
    const float* __restrict__ bv)
{
    extern __shared__ float smf[];
    const int zz = blockIdx.z >> 3;
    const int b  = blockIdx.z & 7;
    if (zz == 0)      proj_body<128>(g_qi, g_wq, bq, g_q, 2, b, smf);
    else if (zz == 1) proj_body<128>(g_ki, g_wk, bk, g_k, 5, b, smf);
    else              proj_body<128>(g_vi, g_wv, bv, g_v, 1, b, smf);
}

// Final projection: 64-row o-tiles -> 512 CTAs -> 1.73 waves.
__global__ void __launch_bounds__(256, 2) proj_out_kernel(
    const float* __restrict__ bias, float* __restrict__ out)
{
    extern __shared__ float smf[];
    proj_body<64>(g_x, g_wm, bias, out, 0, blockIdx.z, smf);
}

// ===========================================================================
// Fused attention (R11, protected): 256 threads, 8 warps x 16 query rows,
// all-tf32, P register-resident, all B-fragments via LDS.64
// (K from paired layout; V natural — PV pair == consecutive keys).
// cp.async K/V double buffer; Q A-frags in registers. Softmax without max
// subtraction (scores bounded; exact math). Output stored tf32-rounded.
// ===========================================================================
#define QT 128
#define KTILE 64
#define NTILES (NN / KTILE)

#define AK2 136
#define AVS 72
#define KBW (32 * AK2)
#define VBW (64 * AVS)
#define OFF_K 0
#define OFF_V (2 * KBW)
#define ATTN_SMEM ((OFF_V + 2 * VBW) * 4)   // 71,680 bytes

__global__ void __launch_bounds__(256, 2) attn_mma_kernel(
    const float* __restrict__ Q, const float* __restrict__ K,
    const float* __restrict__ V, float* __restrict__ O)
{
    extern __shared__ float smf[];
    uint32_t* smw = (uint32_t*)smf;
    const uint32_t sb = smem_u32(smf);

    const int tid  = threadIdx.x;
    const int warp = tid >> 5;
    const int lane = tid & 31;
    const int j    = lane & 3;
    const int r    = lane >> 2;

    const int bid = blockIdx.x;
    const int q0  = (bid & 15) * QT;
    const int h   = (bid >> 4) & 3;
    const int b   = bid >> 6;
    const size_t base = (size_t)b * DD * NN + (size_t)h * NN;

    const int kr   = tid >> 3;
    const int kseg = (tid & 7) * 16;
    const float* Kgc = K + (size_t)b * DD * NN + (size_t)h * 64 * NN
                     + (size_t)kr * 2 * NN + kseg;
    const uint32_t kaddr0 = sb + (OFF_K + kr * AK2 + kseg) * 4;
    const int vr   = tid >> 2;
    const int vseg = (tid & 3) * 16;
    const float* Vgc = V + base + (size_t)vr * HH * NN + vseg;
    const uint32_t vaddr0 = sb + (OFF_V + vr * AVS + vseg) * 4;

#pragma unroll
    for (int i = 0; i < 4; i++) {
        cp16(kaddr0 + i * 16, Kgc + i * 4);
        cp16(vaddr0 + i * 16, Vgc + i * 4);
    }
    CP_COMMIT();

    const int qrow = warp * 16 + r;
    uint32_t qa[8][4];
    {
        const float* Qg = Q + base + q0 + qrow;
#pragma unroll
        for (int kc = 0; kc < 8; kc++) {
            const float* p0 = Qg + (size_t)(kc * 8 + j) * HH * NN;
            const float* p1 = Qg + (size_t)(kc * 8 + j + 4) * HH * NN;
            qa[kc][0] = __float_as_uint(p0[0]);
            qa[kc][1] = __float_as_uint(p0[8]);
            qa[kc][2] = __float_as_uint(p1[0]);
            qa[kc][3] = __float_as_uint(p1[8]);
        }
    }

    float oacc[8][4];
#pragma unroll
    for (int nc = 0; nc < 8; nc++)
#pragma unroll
        for (int c = 0; c < 4; c++) oacc[nc][c] = 0.f;
    float rs0 = 0.f, rs1 = 0.f;

    for (int t = 0; t < NTILES; t++) {
        const int cur = t & 1;

        CP_WAIT0();
        __syncthreads();

        if (t + 1 < NTILES) {
            const int nxt = (t + 1) & 1;
            const int kn = (t + 1) * KTILE;
#pragma unroll
            for (int i = 0; i < 4; i++) {
                cp16(kaddr0 + (nxt * KBW) * 4 + i * 16, Kgc + kn * 2 + i * 4);
                cp16(vaddr0 + (nxt * VBW) * 4 + i * 16, Vgc + kn + i * 4);
            }
            CP_COMMIT();
        }

        const uint32_t* Kb = smw + OFF_K + cur * KBW;
        const uint32_t* Vb = smw + OFF_V + cur * VBW;

        float s[8][4];
#pragma unroll
        for (int nc = 0; nc < 8; nc++)
#pragma unroll
            for (int c = 0; c < 4; c++) s[nc][c] = 0.f;

#pragma unroll
        for (int kc = 0; kc < 8; kc++) {
            const int pr = kc * 4 + j;
#pragma unroll
            for (int nc = 0; nc < 8; nc++) {
                const uint2 bb =
                    *(const uint2*)&Kb[pr * AK2 + (nc * 8 + r) * 2];
                mma_tf32(s[nc], qa[kc][0], qa[kc][1], qa[kc][2], qa[kc][3],
                         bb.x, bb.y);
            }
        }

#pragma unroll
        for (int nc = 0; nc < 8; nc++) {
            const uint32_t u0 = f2tf32(__expf(s[nc][0]));
            const uint32_t u1 = f2tf32(__expf(s[nc][1]));
            const uint32_t u2 = f2tf32(__expf(s[nc][2]));
            const uint32_t u3 = f2tf32(__expf(s[nc][3]));
            rs0 += __uint_as_float(u0) + __uint_as_float(u1);
            rs1 += __uint_as_float(u2) + __uint_as_float(u3);
            s[nc][0] = __uint_as_float(u0);
            s[nc][1] = __uint_as_float(u1);
            s[nc][2] = __uint_as_float(u2);
            s[nc][3] = __uint_as_float(u3);
        }

#pragma unroll
        for (int kc = 0; kc < 8; kc++) {
            const uint32_t a0 = __float_as_uint(s[kc][0]);
            const uint32_t a1 = __float_as_uint(s[kc][2]);
            const uint32_t a2 = __float_as_uint(s[kc][1]);
            const uint32_t a3 = __float_as_uint(s[kc][3]);
            const int kk = kc * 8 + 2 * j;
#pragma unroll
            for (int nc = 0; nc < 8; nc++) {
                const uint2 vb =
                    *(const uint2*)&Vb[(nc * 8 + r) * AVS + kk];
                mma_tf32(oacc[nc], a0, a1, a2, a3, vb.x, vb.y);
            }
        }
    }

    rs0 += __shfl_xor_sync(0xffffffffu, rs0, 1);
    rs0 += __shfl_xor_sync(0xffffffffu, rs0, 2);
    rs1 += __shfl_xor_sync(0xffffffffu, rs1, 1);
    rs1 += __shfl_xor_sync(0xffffffffu, rs1, 2);
    const float inv0 = 1.0f / rs0;
    const float inv1 = 1.0f / rs1;

    __syncthreads();
#pragma unroll
    for (int nc = 0; nc < 8; nc++) {
        const int col = nc * 8 + 2 * j;
        smf[qrow * 68 + col]           = oacc[nc][0] * inv0;
        smf[qrow * 68 + col + 1]       = oacc[nc][1] * inv0;
        smf[(qrow + 8) * 68 + col]     = oacc[nc][2] * inv1;
        smf[(qrow + 8) * 68 + col + 1] = oacc[nc][3] * inv1;
    }
    __syncthreads();
    for (int idx = tid; idx < 64 * QT; idx += 256) {
        const int dh = idx >> 7;
        const int q  = idx & 127;
        O[base + (size_t)dh * HH * NN + q0 + q] =
            __uint_as_float(f2tf32(smf[q * 68 + dh]));
    }
}

// ===========================================================================
// Launch
// ===========================================================================
extern "C" void kernel_launch(void* const* d_in, const int* in_sizes, int n_in,
                              void* d_out, int out_size)
{
    const float* query = (const float*)d_in[0];
    const float* key   = (const float*)d_in[1];
    const float* value = (const float*)d_in[2];
    const float* bq = (const float*)d_in[4];
    const float* bk = (const float*)d_in[6];
    const float* bv = (const float*)d_in[8];
    const float* bm = (const float*)d_in[10];
    const float* Wq = (const float*)d_in[3];
    const float* Wk = (const float*)d_in[5];
    const float* Wv = (const float*)d_in[7];
    const float* Wm = (const float*)d_in[9];
    float* out = (float*)d_out;

    static float *pq = nullptr, *pk = nullptr, *pv = nullptr, *px = nullptr;
    static bool init_done = false;
    if (!init_done) {
        cudaGetSymbolAddress((void**)&pq, g_q);
        cudaGetSymbolAddress((void**)&pk, g_k);
        cudaGetSymbolAddress((void**)&pv, g_v);
        cudaGetSymbolAddress((void**)&px, g_x);
        cudaFuncSetAttribute(attn_mma_kernel,
                             cudaFuncAttributeMaxDynamicSharedMemorySize,
                             ATTN_SMEM);
        cudaFuncSetAttribute(proj_qkv_kernel,
                             cudaFuncAttributeMaxDynamicSharedMemorySize, PROJ_SMEM);
        cudaFuncSetAttribute(proj_out_kernel,
                             cudaFuncAttributeMaxDynamicSharedMemorySize, PROJ_SMEM);
        init_done = true;
    }

    prep_kernel<<<(BB * DD * NN / 4 + 255) / 256, 256>>>(
        query, key, value, Wq, Wk, Wv, Wm);

    dim3 qkvgrid(NN / 128, DD / 128, 3 * BB);   // (16, 2, 24) = 768 CTAs
    proj_qkv_kernel<<<qkvgrid, 256, PROJ_SMEM>>>(bq, bk, bv);

    attn_mma_kernel<<<BB * HH * (NN / 128), 256, ATTN_SMEM>>>(pq, pk, pv, px);

    dim3 ogrid(NN / 128, DD / 64, BB);          // (16, 4, 8) = 512 CTAs
    proj_out_kernel<<<ogrid, 256, PROJ_SMEM>>>(bm, out);
}

// round 13
// speedup vs baseline: 1.0856x; 1.0219x over previous
#include <cuda_runtime.h>
#include <cstdint>

// Problem constants
#define BB 8
#define DD 256
#define NN 2048
#define HH 4
#define HD 64

// Scratch — __device__ globals per allocation rules
__device__ float g_qi[BB * DD * NN];  // tf32-rounded raw inputs
__device__ float g_ki[BB * DD * NN];
__device__ float g_vi[BB * DD * NN];
__device__ float g_wq[DD * DD];       // tf32-rounded weights
__device__ float g_wk[DD * DD];
__device__ float g_wv[DD * DD];
__device__ float g_wm[DD * DD];
__device__ float g_q[BB * DD * NN];   // Q proj: tf32(0.125*log2e*val)
__device__ float g_k[BB * DD * NN];   // K proj: tf32, paired [b][h][pr][n][e]
__device__ float g_v[BB * DD * NN];   // V proj: tf32, natural layout
__device__ float g_x[BB * DD * NN];   // attention out (tf32-rounded)

__device__ __forceinline__ uint32_t f2tf32(float f) {
    uint32_t u;
    asm("cvt.rna.tf32.f32 %0, %1;" : "=r"(u) : "f"(f));
    return u;
}

__device__ __forceinline__ float ex2f(float f) {
    float r;
    asm("ex2.approx.f32 %0, %1;" : "=f"(r) : "f"(f));
    return r;
}

__device__ __forceinline__ uint32_t smem_u32(const void* p) {
    uint32_t a;
    asm("{ .reg .u64 t; cvta.to.shared.u64 t, %1; cvt.u32.u64 %0, t; }"
        : "=r"(a) : "l"(p));
    return a;
}

__device__ __forceinline__ void cp16(uint32_t saddr, const float* g) {
    uint64_t ga;
    asm("cvta.to.global.u64 %0, %1;" : "=l"(ga) : "l"(g));
    asm volatile("cp.async.ca.shared.global [%0], [%1], 16;"
                 :: "r"(saddr), "l"(ga));
}
#define CP_COMMIT() asm volatile("cp.async.commit_group;" ::: "memory")
#define CP_WAIT0()  asm volatile("cp.async.wait_group 0;" ::: "memory")

// tf32 m16n8k8: D += A*B
__device__ __forceinline__ void mma_tf32(float d[4],
                                         uint32_t a0, uint32_t a1,
                                         uint32_t a2, uint32_t a3,
                                         uint32_t b0, uint32_t b1) {
    asm volatile(
        "mma.sync.aligned.m16n8k8.row.col.f32.tf32.tf32.f32 "
        "{%0,%1,%2,%3}, {%4,%5,%6,%7}, {%8,%9}, {%0,%1,%2,%3};"
        : "+f"(d[0]), "+f"(d[1]), "+f"(d[2]), "+f"(d[3])
        : "r"(a0), "r"(a1), "r"(a2), "r"(a3), "r"(b0), "r"(b1));
}

// ===========================================================================
// Prep: RNA-round inputs (q,k,v) and the four weight matrices to tf32 bits.
// ===========================================================================
__global__ void __launch_bounds__(256) prep_kernel(
    const float* __restrict__ q, const float* __restrict__ k,
    const float* __restrict__ v,
    const float* __restrict__ wq, const float* __restrict__ wk,
    const float* __restrict__ wv, const float* __restrict__ wm)
{
    const int i = blockIdx.x * 256 + threadIdx.x;   // float4 index
    if (i < (BB * DD * NN) / 4) {
        float4 a = ((const float4*)q)[i];
        float4 b = ((const float4*)k)[i];
        float4 c = ((const float4*)v)[i];
        a.x = __uint_as_float(f2tf32(a.x)); a.y = __uint_as_float(f2tf32(a.y));
        a.z = __uint_as_float(f2tf32(a.z)); a.w = __uint_as_float(f2tf32(a.w));
        b.x = __uint_as_float(f2tf32(b.x)); b.y = __uint_as_float(f2tf32(b.y));
        b.z = __uint_as_float(f2tf32(b.z)); b.w = __uint_as_float(f2tf32(b.w));
        c.x = __uint_as_float(f2tf32(c.x)); c.y = __uint_as_float(f2tf32(c.y));
        c.z = __uint_as_float(f2tf32(c.z)); c.w = __uint_as_float(f2tf32(c.w));
        ((float4*)g_qi)[i] = a;
        ((float4*)g_ki)[i] = b;
        ((float4*)g_vi)[i] = c;
    }
    if (i < (DD * DD) / 4) {
        float4 a = ((const float4*)wq)[i];
        float4 b = ((const float4*)wk)[i];
        float4 c = ((const float4*)wv)[i];
        float4 d = ((const float4*)wm)[i];
        a.x = __uint_as_float(f2tf32(a.x)); a.y = __uint_as_float(f2tf32(a.y));
        a.z = __uint_as_float(f2tf32(a.z)); a.w = __uint_as_float(f2tf32(a.w));
        b.x = __uint_as_float(f2tf32(b.x)); b.y = __uint_as_float(f2tf32(b.y));
        b.z = __uint_as_float(f2tf32(b.z)); b.w = __uint_as_float(f2tf32(b.w));
        c.x = __uint_as_float(f2tf32(c.x)); c.y = __uint_as_float(f2tf32(c.y));
        c.z = __uint_as_float(f2tf32(c.z)); c.w = __uint_as_float(f2tf32(c.w));
        d.x = __uint_as_float(f2tf32(d.x)); d.y = __uint_as_float(f2tf32(d.y));
        d.z = __uint_as_float(f2tf32(d.z)); d.w = __uint_as_float(f2tf32(d.w));
        ((float4*)g_wq)[i] = a;
        ((float4*)g_wk)[i] = b;
        ((float4*)g_wv)[i] = c;
        ((float4*)g_wm)[i] = d;
    }
}

// ===========================================================================
// Projection GEMM body (cp.async, zero cvt in loop). Operands pre-rounded.
// 256 threads = 4 rg x 2 cg; 128x128 output tile; 32-row double-buffered
// chunks.
// omode: 0 = plain fp32, 1 = tf32 bits, 2 = tf32(0.125*log2e*val),
//        5 = tf32 bits + K-paired gmem layout [b][h][pr][n][e]
// ===========================================================================
#define PS 136
#define CHW (32 * PS)
#define PXO (2 * CHW)
#define PROJ_SMEM (4 * CHW * 4)          // 69,632 bytes
#define QSCALE 0.1803368801111446f      // 0.125 * log2(e)

__device__ __forceinline__ void proj_body(
    const float* __restrict__ X, const float* __restrict__ W,
    const float* __restrict__ bias, float* __restrict__ out,
    int omode, int b, float* smf)
{
    uint32_t* smw = (uint32_t*)smf;
    const uint32_t sb = smem_u32(smf);

    const int tid  = threadIdx.x;
    const int warp = tid >> 5;
    const int lane = tid & 31;
    const int j    = lane & 3;
    const int r    = lane >> 2;
    const int rg   = warp & 3;
    const int cg   = warp >> 2;

    const int o0 = blockIdx.y * 128;
    const int n0 = blockIdx.x * 128;
    const float* Xb = X + (size_t)b * DD * NN;

    const int srow = tid >> 3;
    const int sseg = (tid & 7) * 16;
    const uint32_t wdst = sb + (srow * PS + sseg) * 4;
    const uint32_t xdst = sb + (PXO + srow * PS + sseg) * 4;

#pragma unroll
    for (int i = 0; i < 4; i++) {
        cp16(wdst + i * 16, W  + (size_t)srow * DD + o0 + sseg + i * 4);
        cp16(xdst + i * 16, Xb + (size_t)srow * NN + n0 + sseg + i * 4);
    }
    CP_COMMIT();

    float acc[2][8][4];
#pragma unroll
    for (int mt = 0; mt < 2; mt++)
#pragma unroll
        for (int nc = 0; nc < 8; nc++)
#pragma unroll
            for (int c = 0; c < 4; c++) acc[mt][nc][c] = 0.f;

    for (int ch = 0; ch < 8; ch++) {
        const int cur = ch & 1;
        CP_WAIT0();
        __syncthreads();

        if (ch + 1 < 8) {
            const int nxt = (ch + 1) & 1;
            const int d0c = (ch + 1) * 32;
#pragma unroll
            for (int i = 0; i < 4; i++) {
                cp16(wdst + nxt * CHW * 4 + i * 16,
                     W  + (size_t)(d0c + srow) * DD + o0 + sseg + i * 4);
                cp16(xdst + nxt * CHW * 4 + i * 16,
                     Xb + (size_t)(d0c + srow) * NN + n0 + sseg + i * 4);
            }
            CP_COMMIT();
        }

        const uint32_t* Wt = smw + cur * CHW;
        const uint32_t* Xt = smw + PXO + cur * CHW;

#pragma unroll
        for (int kc = 0; kc < 4; kc++) {
            const int d0 = kc * 8;
            uint32_t a[2][4];
#pragma unroll
            for (int mt = 0; mt < 2; mt++) {
                const int ob = rg * 32 + mt * 16 + r;
                a[mt][0] = Wt[(d0 + j) * PS + ob];
                a[mt][1] = Wt[(d0 + j) * PS + ob + 8];
                a[mt][2] = Wt[(d0 + j + 4) * PS + ob];
                a[mt][3] = Wt[(d0 + j + 4) * PS + ob + 8];
            }
#pragma unroll
            for (int nc = 0; nc < 8; nc++) {
                const int nb = cg * 64 + nc * 8 + r;
                const uint32_t b0 = Xt[(d0 + j) * PS + nb];
                const uint32_t b1 = Xt[(d0 + j + 4) * PS + nb];
                mma_tf32(acc[0][nc], a[0][0], a[0][1], a[0][2], a[0][3], b0, b1);
                mma_tf32(acc[1][nc], a[1][0], a[1][1], a[1][2], a[1][3], b0, b1);
            }
        }
        __syncthreads();
    }

#pragma unroll
    for (int mt = 0; mt < 2; mt++) {
        const int orow = o0 + rg * 32 + mt * 16 + r;
        const float bi0 = bias[orow];
        const float bi1 = bias[orow + 8];
#pragma unroll
        for (int nc = 0; nc < 8; nc++) {
            float v00 = acc[mt][nc][0] + bi0, v01 = acc[mt][nc][1] + bi0;
            float v10 = acc[mt][nc][2] + bi1, v11 = acc[mt][nc][3] + bi1;
            if (omode == 2) {
                v00 *= QSCALE; v01 *= QSCALE; v10 *= QSCALE; v11 *= QSCALE;
            }
            if (omode >= 1) {
                v00 = __uint_as_float(f2tf32(v00));
                v01 = __uint_as_float(f2tf32(v01));
                v10 = __uint_as_float(f2tf32(v10));
                v11 = __uint_as_float(f2tf32(v11));
            }
            const int ncol = n0 + cg * 64 + nc * 8 + 2 * j;
            if (omode == 5) {
                // K-paired layout: idx = b*DD*NN + h*64*NN + pr*2*NN + n*2 + e
#pragma unroll
                for (int rr = 0; rr < 2; rr++) {
                    const int o = orow + rr * 8;
                    const int h  = o & 3;
                    const int dh = o >> 2;
                    const int pr = ((dh >> 3) << 2) | (dh & 3);
                    const int e  = (dh >> 2) & 1;
                    float* dst = out + (size_t)b * DD * NN
                               + (size_t)h * 64 * NN + (size_t)pr * 2 * NN + e;
                    const float a0 = rr ? v10 : v00;
                    const float a1 = rr ? v11 : v01;
                    dst[(size_t)ncol * 2]       = a0;
                    dst[(size_t)(ncol + 1) * 2] = a1;
                }
            } else {
                float* row0 = out + (size_t)b * DD * NN + (size_t)orow * NN + ncol;
                float* row1 = row0 + 8 * NN;
                *(float2*)row0 = make_float2(v00, v01);
                *(float2*)row1 = make_float2(v10, v11);
            }
        }
    }
}

// Merged Q/K/V projection: z = which*8 + b. 768 CTAs -> 2.6 waves.
__global__ void __launch_bounds__(256, 2) proj_qkv_kernel(
    const float* __restrict__ bq, const float* __restrict__ bk,
    const float* __restrict__ bv)
{
    extern __shared__ float smf[];
    const int zz = blockIdx.z >> 3;
    const int b  = blockIdx.z & 7;
    if (zz == 0)      proj_body(g_qi, g_wq, bq, g_q, 2, b, smf);
    else if (zz == 1) proj_body(g_ki, g_wk, bk, g_k, 5, b, smf);
    else              proj_body(g_vi, g_wv, bv, g_v, 1, b, smf);
}

// Final projection (plain fp32 out), 128-row tiles (R11-proven config).
__global__ void __launch_bounds__(256, 2) proj_out_kernel(
    const float* __restrict__ bias, float* __restrict__ out)
{
    extern __shared__ float smf[];
    proj_body(g_x, g_wm, bias, out, 0, blockIdx.z, smf);
}

// ===========================================================================
// Fused attention: 256 threads, 8 warps x 16 query rows, all-tf32,
// P register-resident, all B-fragments via LDS.64. exp via bare ex2
// (log2e folded into Q projection scale). Softmax without max subtraction
// (scores bounded; exact math). Output stored tf32-rounded.
// ===========================================================================
#define QT 128
#define KTILE 64
#define NTILES (NN / KTILE)

#define AK2 136
#define AVS 72
#define KBW (32 * AK2)
#define VBW (64 * AVS)
#define OFF_K 0
#define OFF_V (2 * KBW)
#define ATTN_SMEM ((OFF_V + 2 * VBW) * 4)   // 71,680 bytes

__global__ void __launch_bounds__(256, 2) attn_mma_kernel(
    const float* __restrict__ Q, const float* __restrict__ K,
    const float* __restrict__ V, float* __restrict__ O)
{
    extern __shared__ float smf[];
    uint32_t* smw = (uint32_t*)smf;
    const uint32_t sb = smem_u32(smf);

    const int tid  = threadIdx.x;
    const int warp = tid >> 5;
    const int lane = tid & 31;
    const int j    = lane & 3;
    const int r    = lane >> 2;

    const int bid = blockIdx.x;
    const int q0  = (bid & 15) * QT;
    const int h   = (bid >> 4) & 3;
    const int b   = bid >> 6;
    const size_t base = (size_t)b * DD * NN + (size_t)h * NN;

    const int kr   = tid >> 3;
    const int kseg = (tid & 7) * 16;
    const float* Kgc = K + (size_t)b * DD * NN + (size_t)h * 64 * NN
                     + (size_t)kr * 2 * NN + kseg;
    const uint32_t kaddr0 = sb + (OFF_K + kr * AK2 + kseg) * 4;
    const int vr   = tid >> 2;
    const int vseg = (tid & 3) * 16;
    const float* Vgc = V + base + (size_t)vr * HH * NN + vseg;
    const uint32_t vaddr0 = sb + (OFF_V + vr * AVS + vseg) * 4;

#pragma unroll
    for (int i = 0; i < 4; i++) {
        cp16(kaddr0 + i * 16, Kgc + i * 4);
        cp16(vaddr0 + i * 16, Vgc + i * 4);
    }
    CP_COMMIT();

    const int qrow = warp * 16 + r;
    uint32_t qa[8][4];
    {
        const float* Qg = Q + base + q0 + qrow;
#pragma unroll
        for (int kc = 0; kc < 8; kc++) {
            const float* p0 = Qg + (size_t)(kc * 8 + j) * HH * NN;
            const float* p1 = Qg + (size_t)(kc * 8 + j + 4) * HH * NN;
            qa[kc][0] = __float_as_uint(p0[0]);
            qa[kc][1] = __float_as_uint(p0[8]);
            qa[kc][2] = __float_as_uint(p1[0]);
            qa[kc][3] = __float_as_uint(p1[8]);
        }
    }

    float oacc[8][4];
#pragma unroll
    for (int nc = 0; nc < 8; nc++)
#pragma unroll
        for (int c = 0; c < 4; c++) oacc[nc][c] = 0.f;
    float rsA = 0.f, rsB = 0.f, rsC = 0.f, rsD = 0.f;

    for (int t = 0; t < NTILES; t++) {
        const int cur = t & 1;

        CP_WAIT0();
        __syncthreads();

        if (t + 1 < NTILES) {
            const int nxt = (t + 1) & 1;
            const int kn = (t + 1) * KTILE;
#pragma unroll
            for (int i = 0; i < 4; i++) {
                cp16(kaddr0 + (nxt * KBW) * 4 + i * 16, Kgc + kn * 2 + i * 4);
                cp16(vaddr0 + (nxt * VBW) * 4 + i * 16, Vgc + kn + i * 4);
            }
            CP_COMMIT();
        }

        const uint32_t* Kb = smw + OFF_K + cur * KBW;
        const uint32_t* Vb = smw + OFF_V + cur * VBW;

        float s[8][4];
#pragma unroll
        for (int nc = 0; nc < 8; nc++)
#pragma unroll
            for (int c = 0; c < 4; c++) s[nc][c] = 0.f;

#pragma unroll
        for (int kc = 0; kc < 8; kc++) {
            const int pr = kc * 4 + j;
#pragma unroll
            for (int nc = 0; nc < 8; nc++) {
                const uint2 bb =
                    *(const uint2*)&Kb[pr * AK2 + (nc * 8 + r) * 2];
                mma_tf32(s[nc], qa[kc][0], qa[kc][1], qa[kc][2], qa[kc][3],
                         bb.x, bb.y);
            }
        }

        // exp2 (log2e pre-folded), tf32-rounded; rowsums in 4 accumulators
#pragma unroll
        for (int nc = 0; nc < 8; nc++) {
            const uint32_t u0 = f2tf32(ex2f(s[nc][0]));
            const uint32_t u1 = f2tf32(ex2f(s[nc][1]));
            const uint32_t u2 = f2tf32(ex2f(s[nc][2]));
            const uint32_t u3 = f2tf32(ex2f(s[nc][3]));
            if (nc & 1) {
                rsB += __uint_as_float(u0) + __uint_as_float(u1);
                rsD += __uint_as_float(u2) + __uint_as_float(u3);
            } else {
                rsA += __uint_as_float(u0) + __uint_as_float(u1);
                rsC += __uint_as_float(u2) + __uint_as_float(u3);
            }
            s[nc][0] = __uint_as_float(u0);
            s[nc][1] = __uint_as_float(u1);
            s[nc][2] = __uint_as_float(u2);
            s[nc][3] = __uint_as_float(u3);
        }

#pragma unroll
        for (int kc = 0; kc < 8; kc++) {
            const uint32_t a0 = __float_as_uint(s[kc][0]);
            const uint32_t a1 = __float_as_uint(s[kc][2]);
            const uint32_t a2 = __float_as_uint(s[kc][1]);
            const uint32_t a3 = __float_as_uint(s[kc][3]);
            const int kk = kc * 8 + 2 * j;
#pragma unroll
            for (int nc = 0; nc < 8; nc++) {
                const uint2 vb =
                    *(const uint2*)&Vb[(nc * 8 + r) * AVS + kk];
                mma_tf32(oacc[nc], a0, a1, a2, a3, vb.x, vb.y);
            }
        }
    }

    float rs0 = rsA + rsB;
    float rs1 = rsC + rsD;
    rs0 += __shfl_xor_sync(0xffffffffu, rs0, 1);
    rs0 += __shfl_xor_sync(0xffffffffu, rs0, 2);
    rs1 += __shfl_xor_sync(0xffffffffu, rs1, 1);
    rs1 += __shfl_xor_sync(0xffffffffu, rs1, 2);
    const float inv0 = 1.0f / rs0;
    const float inv1 = 1.0f / rs1;

    __syncthreads();
#pragma unroll
    for (int nc = 0; nc < 8; nc++) {
        const int col = nc * 8 + 2 * j;
        smf[qrow * 68 + col]           = oacc[nc][0] * inv0;
        smf[qrow * 68 + col + 1]       = oacc[nc][1] * inv0;
        smf[(qrow + 8) * 68 + col]     = oacc[nc][2] * inv1;
        smf[(qrow + 8) * 68 + col + 1] = oacc[nc][3] * inv1;
    }
    __syncthreads();
    for (int idx = tid; idx < 64 * QT; idx += 256) {
        const int dh = idx >> 7;
        const int q  = idx & 127;
        O[base + (size_t)dh * HH * NN + q0 + q] =
            __uint_as_float(f2tf32(smf[q * 68 + dh]));
    }
}

// ===========================================================================
// Launch
// ===========================================================================
extern "C" void kernel_launch(void* const* d_in, const int* in_sizes, int n_in,
                              void* d_out, int out_size)
{
    const float* query = (const float*)d_in[0];
    const float* key   = (const float*)d_in[1];
    const float* value = (const float*)d_in[2];
    const float* Wq = (const float*)d_in[3];
    const float* bq = (const float*)d_in[4];
    const float* Wk = (const float*)d_in[5];
    const float* bk = (const float*)d_in[6];
    const float* Wv = (const float*)d_in[7];
    const float* bv = (const float*)d_in[8];
    const float* Wm = (const float*)d_in[9];
    const float* bm = (const float*)d_in[10];
    float* out = (float*)d_out;

    static float *pq = nullptr, *pk = nullptr, *pv = nullptr, *px = nullptr;
    static bool init_done = false;
    if (!init_done) {
        cudaGetSymbolAddress((void**)&pq, g_q);
        cudaGetSymbolAddress((void**)&pk, g_k);
        cudaGetSymbolAddress((void**)&pv, g_v);
        cudaGetSymbolAddress((void**)&px, g_x);
        cudaFuncSetAttribute(attn_mma_kernel,
                             cudaFuncAttributeMaxDynamicSharedMemorySize,
                             ATTN_SMEM);
        cudaFuncSetAttribute(proj_qkv_kernel,
                             cudaFuncAttributeMaxDynamicSharedMemorySize, PROJ_SMEM);
        cudaFuncSetAttribute(proj_out_kernel,
                             cudaFuncAttributeMaxDynamicSharedMemorySize, PROJ_SMEM);
        init_done = true;
    }

    prep_kernel<<<(BB * DD * NN / 4 + 255) / 256, 256>>>(
        query, key, value, Wq, Wk, Wv, Wm);

    dim3 qkvgrid(NN / 128, DD / 128, 3 * BB);   // (16, 2, 24) = 768 CTAs
    proj_qkv_kernel<<<qkvgrid, 256, PROJ_SMEM>>>(bq, bk, bv);

    attn_mma_kernel<<<BB * HH * (NN / 128), 256, ATTN_SMEM>>>(pq, pk, pv, px);

    dim3 ogrid(NN / 128, DD / 128, BB);         // (16, 2, 8) = 256 CTAs
    proj_out_kernel<<<ogrid, 256, PROJ_SMEM>>>(bm, out);
}

// round 14
// speedup vs baseline: 1.2797x; 1.1788x over previous
#include <cuda_runtime.h>
#include <cstdint>

// Problem constants
#define BB 8
#define DD 256
#define NN 2048
#define HH 4
#define HD 64

// Scratch — __device__ globals per allocation rules
__device__ float g_qi[BB * DD * NN];  // tf32-rounded raw inputs
__device__ float g_ki[BB * DD * NN];
__device__ float g_vi[BB * DD * NN];
__device__ float g_wq[DD * DD];       // tf32-rounded weights
__device__ float g_wk[DD * DD];
__device__ float g_wv[DD * DD];
__device__ float g_wm[DD * DD];
__device__ float g_q[BB * DD * NN];   // Q proj: tf32(0.125*log2e*val)
__device__ float g_k[BB * DD * NN];   // K proj: tf32, paired [b][h][pr][n][e]
__device__ float g_v[BB * DD * NN];   // V proj: tf32, natural layout
__device__ float g_x[BB * DD * NN];   // attention out (tf32-rounded)

__device__ __forceinline__ uint32_t f2tf32(float f) {
    uint32_t u;
    asm("cvt.rna.tf32.f32 %0, %1;" : "=r"(u) : "f"(f));
    return u;
}

__device__ __forceinline__ float ex2f(float f) {
    float r;
    asm("ex2.approx.f32 %0, %1;" : "=f"(r) : "f"(f));
    return r;
}

__device__ __forceinline__ uint32_t smem_u32(const void* p) {
    uint32_t a;
    asm("{ .reg .u64 t; cvta.to.shared.u64 t, %1; cvt.u32.u64 %0, t; }"
        : "=r"(a) : "l"(p));
    return a;
}

__device__ __forceinline__ void cp16(uint32_t saddr, const float* g) {
    uint64_t ga;
    asm("cvta.to.global.u64 %0, %1;" : "=l"(ga) : "l"(g));
    asm volatile("cp.async.ca.shared.global [%0], [%1], 16;"
                 :: "r"(saddr), "l"(ga));
}
#define CP_COMMIT() asm volatile("cp.async.commit_group;" ::: "memory")
#define CP_WAIT0()  asm volatile("cp.async.wait_group 0;" ::: "memory")

// tf32 m16n8k8: D += A*B
__device__ __forceinline__ void mma_tf32(float d[4],
                                         uint32_t a0, uint32_t a1,
                                         uint32_t a2, uint32_t a3,
                                         uint32_t b0, uint32_t b1) {
    asm volatile(
        "mma.sync.aligned.m16n8k8.row.col.f32.tf32.tf32.f32 "
        "{%0,%1,%2,%3}, {%4,%5,%6,%7}, {%8,%9}, {%0,%1,%2,%3};"
        : "+f"(d[0]), "+f"(d[1]), "+f"(d[2]), "+f"(d[3])
        : "r"(a0), "r"(a1), "r"(a2), "r"(a3), "r"(b0), "r"(b1));
}

// ===========================================================================
// Prep: RNA-round inputs (q,k,v) and the four weight matrices to tf32 bits.
// ===========================================================================
__global__ void __launch_bounds__(256) prep_kernel(
    const float* __restrict__ q, const float* __restrict__ k,
    const float* __restrict__ v,
    const float* __restrict__ wq, const float* __restrict__ wk,
    const float* __restrict__ wv, const float* __restrict__ wm)
{
    const int i = blockIdx.x * 256 + threadIdx.x;   // float4 index
    if (i < (BB * DD * NN) / 4) {
        float4 a = ((const float4*)q)[i];
        float4 b = ((const float4*)k)[i];
        float4 c = ((const float4*)v)[i];
        a.x = __uint_as_float(f2tf32(a.x)); a.y = __uint_as_float(f2tf32(a.y));
        a.z = __uint_as_float(f2tf32(a.z)); a.w = __uint_as_float(f2tf32(a.w));
        b.x = __uint_as_float(f2tf32(b.x)); b.y = __uint_as_float(f2tf32(b.y));
        b.z = __uint_as_float(f2tf32(b.z)); b.w = __uint_as_float(f2tf32(b.w));
        c.x = __uint_as_float(f2tf32(c.x)); c.y = __uint_as_float(f2tf32(c.y));
        c.z = __uint_as_float(f2tf32(c.z)); c.w = __uint_as_float(f2tf32(c.w));
        ((float4*)g_qi)[i] = a;
        ((float4*)g_ki)[i] = b;
        ((float4*)g_vi)[i] = c;
    }
    if (i < (DD * DD) / 4) {
        float4 a = ((const float4*)wq)[i];
        float4 b = ((const float4*)wk)[i];
        float4 c = ((const float4*)wv)[i];
        float4 d = ((const float4*)wm)[i];
        a.x = __uint_as_float(f2tf32(a.x)); a.y = __uint_as_float(f2tf32(a.y));
        a.z = __uint_as_float(f2tf32(a.z)); a.w = __uint_as_float(f2tf32(a.w));
        b.x = __uint_as_float(f2tf32(b.x)); b.y = __uint_as_float(f2tf32(b.y));
        b.z = __uint_as_float(f2tf32(b.z)); b.w = __uint_as_float(f2tf32(b.w));
        c.x = __uint_as_float(f2tf32(c.x)); c.y = __uint_as_float(f2tf32(c.y));
        c.z = __uint_as_float(f2tf32(c.z)); c.w = __uint_as_float(f2tf32(c.w));
        d.x = __uint_as_float(f2tf32(d.x)); d.y = __uint_as_float(f2tf32(d.y));
        d.z = __uint_as_float(f2tf32(d.z)); d.w = __uint_as_float(f2tf32(d.w));
        ((float4*)g_wq)[i] = a;
        ((float4*)g_wk)[i] = b;
        ((float4*)g_wv)[i] = c;
        ((float4*)g_wm)[i] = d;
    }
}

// ===========================================================================
// Projection GEMM body (cp.async, zero cvt in loop). Operands pre-rounded.
// 256 threads = 4 rg x 2 cg; 128x128 output tile; 32-row double-buffered
// chunks.
// omode: 0 = plain fp32, 1 = tf32 bits, 2 = tf32(0.125*log2e*val),
//        5 = tf32 bits + K-paired gmem layout [b][h][pr][n][e]
// ===========================================================================
#define PS 136
#define CHW (32 * PS)
#define PXO (2 * CHW)
#define PROJ_SMEM (4 * CHW * 4)          // 69,632 bytes
#define QSCALE 0.1803368801111446f      // 0.125 * log2(e)

__device__ __forceinline__ void proj_body(
    const float* __restrict__ X, const float* __restrict__ W,
    const float* __restrict__ bias, float* __restrict__ out,
    int omode, int b, float* smf)
{
    uint32_t* smw = (uint32_t*)smf;
    const uint32_t sb = smem_u32(smf);

    const int tid  = threadIdx.x;
    const int warp = tid >> 5;
    const int lane = tid & 31;
    const int j    = lane & 3;
    const int r    = lane >> 2;
    const int rg   = warp & 3;
    const int cg   = warp >> 2;

    const int o0 = blockIdx.y * 128;
    const int n0 = blockIdx.x * 128;
    const float* Xb = X + (size_t)b * DD * NN;

    const int srow = tid >> 3;
    const int sseg = (tid & 7) * 16;
    const uint32_t wdst = sb + (srow * PS + sseg) * 4;
    const uint32_t xdst = sb + (PXO + srow * PS + sseg) * 4;

#pragma unroll
    for (int i = 0; i < 4; i++) {
        cp16(wdst + i * 16, W  + (size_t)srow * DD + o0 + sseg + i * 4);
        cp16(xdst + i * 16, Xb + (size_t)srow * NN + n0 + sseg + i * 4);
    }
    CP_COMMIT();

    float acc[2][8][4];
#pragma unroll
    for (int mt = 0; mt < 2; mt++)
#pragma unroll
        for (int nc = 0; nc < 8; nc++)
#pragma unroll
            for (int c = 0; c < 4; c++) acc[mt][nc][c] = 0.f;

    for (int ch = 0; ch < 8; ch++) {
        const int cur = ch & 1;
        CP_WAIT0();
        __syncthreads();

        if (ch + 1 < 8) {
            const int nxt = (ch + 1) & 1;
            const int d0c = (ch + 1) * 32;
#pragma unroll
            for (int i = 0; i < 4; i++) {
                cp16(wdst + nxt * CHW * 4 + i * 16,
                     W  + (size_t)(d0c + srow) * DD + o0 + sseg + i * 4);
                cp16(xdst + nxt * CHW * 4 + i * 16,
                     Xb + (size_t)(d0c + srow) * NN + n0 + sseg + i * 4);
            }
            CP_COMMIT();
        }

        const uint32_t* Wt = smw + cur * CHW;
        const uint32_t* Xt = smw + PXO + cur * CHW;

#pragma unroll
        for (int kc = 0; kc < 4; kc++) {
            const int d0 = kc * 8;
            uint32_t a[2][4];
#pragma unroll
            for (int mt = 0; mt < 2; mt++) {
                const int ob = rg * 32 + mt * 16 + r;
                a[mt][0] = Wt[(d0 + j) * PS + ob];
                a[mt][1] = Wt[(d0 + j) * PS + ob + 8];
                a[mt][2] = Wt[(d0 + j + 4) * PS + ob];
                a[mt][3] = Wt[(d0 + j + 4) * PS + ob + 8];
            }
#pragma unroll
            for (int nc = 0; nc < 8; nc++) {
                const int nb = cg * 64 + nc * 8 + r;
                const uint32_t b0 = Xt[(d0 + j) * PS + nb];
                const uint32_t b1 = Xt[(d0 + j + 4) * PS + nb];
                mma_tf32(acc[0][nc], a[0][0], a[0][1], a[0][2], a[0][3], b0, b1);
                mma_tf32(acc[1][nc], a[1][0], a[1][1], a[1][2], a[1][3], b0, b1);
            }
        }
        __syncthreads();
    }

#pragma unroll
    for (int mt = 0; mt < 2; mt++) {
        const int orow = o0 + rg * 32 + mt * 16 + r;
        const float bi0 = bias[orow];
        const float bi1 = bias[orow + 8];
#pragma unroll
        for (int nc = 0; nc < 8; nc++) {
            float v00 = acc[mt][nc][0] + bi0, v01 = acc[mt][nc][1] + bi0;
            float v10 = acc[mt][nc][2] + bi1, v11 = acc[mt][nc][3] + bi1;
            if (omode == 2) {
                v00 *= QSCALE; v01 *= QSCALE; v10 *= QSCALE; v11 *= QSCALE;
            }
            if (omode >= 1) {
                v00 = __uint_as_float(f2tf32(v00));
                v01 = __uint_as_float(f2tf32(v01));
                v10 = __uint_as_float(f2tf32(v10));
                v11 = __uint_as_float(f2tf32(v11));
            }
            const int ncol = n0 + cg * 64 + nc * 8 + 2 * j;
            if (omode == 5) {
                // K-paired layout: idx = b*DD*NN + h*64*NN + pr*2*NN + n*2 + e
#pragma unroll
                for (int rr = 0; rr < 2; rr++) {
                    const int o = orow + rr * 8;
                    const int h  = o & 3;
                    const int dh = o >> 2;
                    const int pr = ((dh >> 3) << 2) | (dh & 3);
                    const int e  = (dh >> 2) & 1;
                    float* dst = out + (size_t)b * DD * NN
                               + (size_t)h * 64 * NN + (size_t)pr * 2 * NN + e;
                    const float a0 = rr ? v10 : v00;
                    const float a1 = rr ? v11 : v01;
                    dst[(size_t)ncol * 2]       = a0;
                    dst[(size_t)(ncol + 1) * 2] = a1;
                }
            } else {
                float* row0 = out + (size_t)b * DD * NN + (size_t)orow * NN + ncol;
                float* row1 = row0 + 8 * NN;
                *(float2*)row0 = make_float2(v00, v01);
                *(float2*)row1 = make_float2(v10, v11);
            }
        }
    }
}

// Merged Q/K/V projection: z = which*8 + b. 768 CTAs -> 2.6 waves.
__global__ void __launch_bounds__(256, 2) proj_qkv_kernel(
    const float* __restrict__ bq, const float* __restrict__ bk,
    const float* __restrict__ bv)
{
    extern __shared__ float smf[];
    const int zz = blockIdx.z >> 3;
    const int b  = blockIdx.z & 7;
    if (zz == 0)      proj_body(g_qi, g_wq, bq, g_q, 2, b, smf);
    else if (zz == 1) proj_body(g_ki, g_wk, bk, g_k, 5, b, smf);
    else              proj_body(g_vi, g_wv, bv, g_v, 1, b, smf);
}

// Final projection (plain fp32 out), 128-row tiles.
__global__ void __launch_bounds__(256, 2) proj_out_kernel(
    const float* __restrict__ bias, float* __restrict__ out)
{
    extern __shared__ float smf[];
    proj_body(g_x, g_wm, bias, out, 0, blockIdx.z, smf);
}

// ===========================================================================
// Fused attention, QT=256: one 512-thread CTA per (b, h, 256-query tile).
// 16 warps x 16 query rows SHARE one K/V staging (half the LDS + STS bytes
// per SM vs two 128-query CTAs). All-tf32, P register-resident, B-frags via
// LDS.64 (K paired layout, V natural), cp.async double buffer, Q A-frags in
// registers, bare ex2 (log2e pre-folded). Softmax without max subtraction.
// Smem 71,680 B; 1 CTA/SM; regs <= 128 (64K RF / 512 thr).
// ===========================================================================
#define QT 256
#define KTILE 64
#define NTILES (NN / KTILE)

#define AK2 136
#define AVS 72
#define KBW (32 * AK2)
#define VBW (64 * AVS)
#define OFF_K 0
#define OFF_V (2 * KBW)
#define ATTN_SMEM ((OFF_V + 2 * VBW) * 4)   // 71,680 bytes

__global__ void __launch_bounds__(512, 1) attn_mma_kernel(
    const float* __restrict__ Q, const float* __restrict__ K,
    const float* __restrict__ V, float* __restrict__ O)
{
    extern __shared__ float smf[];
    uint32_t* smw = (uint32_t*)smf;
    const uint32_t sb = smem_u32(smf);

    const int tid  = threadIdx.x;
    const int warp = tid >> 5;            // 0..15
    const int lane = tid & 31;
    const int j    = lane & 3;
    const int r    = lane >> 2;

    const int bid = blockIdx.x;
    const int q0  = (bid & 7) * QT;       // 8 q-tiles of 256
    const int h   = (bid >> 3) & 3;
    const int b   = bid >> 5;
    const size_t base = (size_t)b * DD * NN + (size_t)h * NN;

    // K staging: 512 threads, thread covers 8 words of one pr-row
    const int kr   = tid >> 4;            // 0..31
    const int kseg = (tid & 15) * 8;      // 0..120
    const float* Kgc = K + (size_t)b * DD * NN + (size_t)h * 64 * NN
                     + (size_t)kr * 2 * NN + kseg;
    const uint32_t kaddr0 = sb + (OFF_K + kr * AK2 + kseg) * 4;
    // V staging: thread covers 8 keys of one dh-row
    const int vr   = tid >> 3;            // 0..63
    const int vseg = (tid & 7) * 8;       // 0..56
    const float* Vgc = V + base + (size_t)vr * HH * NN + vseg;
    const uint32_t vaddr0 = sb + (OFF_V + vr * AVS + vseg) * 4;

#pragma unroll
    for (int i = 0; i < 2; i++) {
        cp16(kaddr0 + i * 16, Kgc + i * 4);
        cp16(vaddr0 + i * 16, Vgc + i * 4);
    }
    CP_COMMIT();

    // Q A-fragments in registers (once)
    const int qrow = warp * 16 + r;       // 0..255
    uint32_t qa[8][4];
    {
        const float* Qg = Q + base + q0 + qrow;
#pragma unroll
        for (int kc = 0; kc < 8; kc++) {
            const float* p0 = Qg + (size_t)(kc * 8 + j) * HH * NN;
            const float* p1 = Qg + (size_t)(kc * 8 + j + 4) * HH * NN;
            qa[kc][0] = __float_as_uint(p0[0]);
            qa[kc][1] = __float_as_uint(p0[8]);
            qa[kc][2] = __float_as_uint(p1[0]);
            qa[kc][3] = __float_as_uint(p1[8]);
        }
    }

    float oacc[8][4];
#pragma unroll
    for (int nc = 0; nc < 8; nc++)
#pragma unroll
        for (int c = 0; c < 4; c++) oacc[nc][c] = 0.f;
    float rsA = 0.f, rsB = 0.f, rsC = 0.f, rsD = 0.f;

    for (int t = 0; t < NTILES; t++) {
        const int cur = t & 1;

        CP_WAIT0();
        __syncthreads();

        if (t + 1 < NTILES) {
            const int nxt = (t + 1) & 1;
            const int kn = (t + 1) * KTILE;
#pragma unroll
            for (int i = 0; i < 2; i++) {
                cp16(kaddr0 + (nxt * KBW) * 4 + i * 16, Kgc + kn * 2 + i * 4);
                cp16(vaddr0 + (nxt * VBW) * 4 + i * 16, Vgc + kn + i * 4);
            }
            CP_COMMIT();
        }

        const uint32_t* Kb = smw + OFF_K + cur * KBW;
        const uint32_t* Vb = smw + OFF_V + cur * VBW;

        // ---- S = Q . K^T ----
        float s[8][4];
#pragma unroll
        for (int nc = 0; nc < 8; nc++)
#pragma unroll
            for (int c = 0; c < 4; c++) s[nc][c] = 0.f;

#pragma unroll
        for (int kc = 0; kc < 8; kc++) {
            const int pr = kc * 4 + j;
#pragma unroll
            for (int nc = 0; nc < 8; nc++) {
                const uint2 bb =
                    *(const uint2*)&Kb[pr * AK2 + (nc * 8 + r) * 2];
                mma_tf32(s[nc], qa[kc][0], qa[kc][1], qa[kc][2], qa[kc][3],
                         bb.x, bb.y);
            }
        }

        // exp2 (log2e pre-folded), tf32-rounded; rowsums in 4 accumulators
#pragma unroll
        for (int nc = 0; nc < 8; nc++) {
            const uint32_t u0 = f2tf32(ex2f(s[nc][0]));
            const uint32_t u1 = f2tf32(ex2f(s[nc][1]));
            const uint32_t u2 = f2tf32(ex2f(s[nc][2]));
            const uint32_t u3 = f2tf32(ex2f(s[nc][3]));
            if (nc & 1) {
                rsB += __uint_as_float(u0) + __uint_as_float(u1);
                rsD += __uint_as_float(u2) + __uint_as_float(u3);
            } else {
                rsA += __uint_as_float(u0) + __uint_as_float(u1);
                rsC += __uint_as_float(u2) + __uint_as_float(u3);
            }
            s[nc][0] = __uint_as_float(u0);
            s[nc][1] = __uint_as_float(u1);
            s[nc][2] = __uint_as_float(u2);
            s[nc][3] = __uint_as_float(u3);
        }

        // ---- O += P . V ----
#pragma unroll
        for (int kc = 0; kc < 8; kc++) {
            const uint32_t a0 = __float_as_uint(s[kc][0]);
            const uint32_t a1 = __float_as_uint(s[kc][2]);
            const uint32_t a2 = __float_as_uint(s[kc][1]);
            const uint32_t a3 = __float_as_uint(s[kc][3]);
            const int kk = kc * 8 + 2 * j;
#pragma unroll
            for (int nc = 0; nc < 8; nc++) {
                const uint2 vb =
                    *(const uint2*)&Vb[(nc * 8 + r) * AVS + kk];
                mma_tf32(oacc[nc], a0, a1, a2, a3, vb.x, vb.y);
            }
        }
    }

    float rs0 = rsA + rsB;
    float rs1 = rsC + rsD;
    rs0 += __shfl_xor_sync(0xffffffffu, rs0, 1);
    rs0 += __shfl_xor_sync(0xffffffffu, rs0, 2);
    rs1 += __shfl_xor_sync(0xffffffffu, rs1, 1);
    rs1 += __shfl_xor_sync(0xffffffffu, rs1, 2);
    const float inv0 = 1.0f / rs0;
    const float inv1 = 1.0f / rs1;

    // Stage normalized O as [q=256][dh] (stride 68) over K/V smem, then store
    __syncthreads();
#pragma unroll
    for (int nc = 0; nc < 8; nc++) {
        const int col = nc * 8 + 2 * j;
        smf[qrow * 68 + col]           = oacc[nc][0] * inv0;
        smf[qrow * 68 + col + 1]       = oacc[nc][1] * inv0;
        smf[(qrow + 8) * 68 + col]     = oacc[nc][2] * inv1;
        smf[(qrow + 8) * 68 + col + 1] = oacc[nc][3] * inv1;
    }
    __syncthreads();
    for (int idx = tid; idx < 64 * QT; idx += 512) {
        const int dh = idx >> 8;
        const int q  = idx & 255;
        O[base + (size_t)dh * HH * NN + q0 + q] =
            __uint_as_float(f2tf32(smf[q * 68 + dh]));
    }
}

// ===========================================================================
// Launch
// ===========================================================================
extern "C" void kernel_launch(void* const* d_in, const int* in_sizes, int n_in,
                              void* d_out, int out_size)
{
    const float* query = (const float*)d_in[0];
    const float* key   = (const float*)d_in[1];
    const float* value = (const float*)d_in[2];
    const float* Wq = (const float*)d_in[3];
    const float* bq = (const float*)d_in[4];
    const float* Wk = (const float*)d_in[5];
    const float* bk = (const float*)d_in[6];
    const float* Wv = (const float*)d_in[7];
    const float* bv = (const float*)d_in[8];
    const float* Wm = (const float*)d_in[9];
    const float* bm = (const float*)d_in[10];
    float* out = (float*)d_out;

    static float *pq = nullptr, *pk = nullptr, *pv = nullptr, *px = nullptr;
    static bool init_done = false;
    if (!init_done) {
        cudaGetSymbolAddress((void**)&pq, g_q);
        cudaGetSymbolAddress((void**)&pk, g_k);
        cudaGetSymbolAddress((void**)&pv, g_v);
        cudaGetSymbolAddress((void**)&px, g_x);
        cudaFuncSetAttribute(attn_mma_kernel,
                             cudaFuncAttributeMaxDynamicSharedMemorySize,
                             ATTN_SMEM);
        cudaFuncSetAttribute(proj_qkv_kernel,
                             cudaFuncAttributeMaxDynamicSharedMemorySize, PROJ_SMEM);
        cudaFuncSetAttribute(proj_out_kernel,
                             cudaFuncAttributeMaxDynamicSharedMemorySize, PROJ_SMEM);
        init_done = true;
    }

    prep_kernel<<<(BB * DD * NN / 4 + 255) / 256, 256>>>(
        query, key, value, Wq, Wk, Wv, Wm);

    dim3 qkvgrid(NN / 128, DD / 128, 3 * BB);   // (16, 2, 24) = 768 CTAs
    proj_qkv_kernel<<<qkvgrid, 256, PROJ_SMEM>>>(bq, bk, bv);

    attn_mma_kernel<<<BB * HH * (NN / QT), 512, ATTN_SMEM>>>(pq, pk, pv, px);

    dim3 ogrid(NN / 128, DD / 128, BB);         // (16, 2, 8) = 256 CTAs
    proj_out_kernel<<<ogrid, 256, PROJ_SMEM>>>(bm, out);
}